// round 2
// baseline (speedup 1.0000x reference)
#include <cuda_runtime.h>
#include <cuda_bf16.h>
#include <math.h>

#define Tn   128
#define Bn   64
#define Hn   1024
#define NUn  256
#define Vn   8000
#define FH   4096   // 4*H

// ------------------------------ scratch (device globals, no allocs) -------
__device__ float g_X[Tn * Bn * NUn];      // embedded inputs, time-major rows (t*64+b)
__device__ float g_GX0[Tn * Bn * FH];     // X@Wx0, then normalized in place (gx0*(x-m)*rstd)
__device__ float g_h0[2][Bn * Hn];        // ping-pong h state layer 0
__device__ float g_c0[Bn * Hn];
__device__ float g_h1[2][Bn * Hn];        // ping-pong h state layer 1
__device__ float g_c1[Bn * Hn];
__device__ float g_H1[Bn * Tn * Hn];      // h1 history in OUTPUT row order (b*T + t)
__device__ float g_Y[Bn * Tn * NUn];      // projection output

__device__ __forceinline__ float sigm(float x) { return 1.0f / (1.0f + expf(-x)); }

// ------------------------------ init: zero recurrent state ----------------
__global__ void k_init() {
    int i = blockIdx.x * 256 + threadIdx.x;   // 65536 threads
    g_h0[0][i] = 0.f; g_h0[1][i] = 0.f; g_c0[i] = 0.f;
    g_h1[0][i] = 0.f; g_h1[1][i] = 0.f; g_c1[i] = 0.f;
}

// ------------------------------ embedding gather --------------------------
__global__ void k_embed(const int* __restrict__ inp, const float* __restrict__ emb) {
    int bid = blockIdx.x;             // t*Bn + b
    int t = bid >> 6, b = bid & 63;
    int u = threadIdx.x;              // 256
    int idx = inp[b * Tn + t];
    g_X[bid * NUn + u] = emb[idx * NUn + u];
}

// ------------------------------ generic fp32 GEMM (+bias) -----------------
// C[M,N] = A[M,K] @ B[K,N] (+ bias[N]).  BM=128, BN=64, BK=32, 256 threads,
// 8x4 per thread. All problem dims divide the tile sizes exactly.
__global__ void k_gemm(const float* __restrict__ A, const float* __restrict__ B,
                       const float* __restrict__ bias, float* __restrict__ C,
                       int M, int N, int K) {
    __shared__ float As[32][129];   // [k][m], padded
    __shared__ float Bs[32][64];    // [k][n]
    int tid = threadIdx.x;
    int bm = blockIdx.y * 128, bn = blockIdx.x * 64;
    int tx = tid & 15;              // col group (4 cols)
    int ty = tid >> 4;              // row group (8 rows)
    float acc[8][4] = {};

    for (int k0 = 0; k0 < K; k0 += 32) {
#pragma unroll
        for (int i = 0; i < 16; i++) {
            int idx = tid + i * 256;          // 0..4095
            int m = idx >> 5, k = idx & 31;
            As[k][m] = A[(long)(bm + m) * K + k0 + k];
        }
#pragma unroll
        for (int i = 0; i < 8; i++) {
            int idx = tid + i * 256;          // 0..2047
            int k = idx >> 6, n = idx & 63;
            Bs[k][n] = B[(long)(k0 + k) * N + bn + n];
        }
        __syncthreads();
#pragma unroll
        for (int k = 0; k < 32; k++) {
            float b4[4];
#pragma unroll
            for (int j = 0; j < 4; j++) b4[j] = Bs[k][tx * 4 + j];
#pragma unroll
            for (int i = 0; i < 8; i++) {
                float a = As[k][ty * 8 + i];
#pragma unroll
                for (int j = 0; j < 4; j++) acc[i][j] += a * b4[j];
            }
        }
        __syncthreads();
    }
#pragma unroll
    for (int i = 0; i < 8; i++) {
        int m = bm + ty * 8 + i;
#pragma unroll
        for (int j = 0; j < 4; j++) {
            int n = bn + tx * 4 + j;
            float v = acc[i][j] + (bias ? bias[n] : 0.f);
            C[(long)m * N + n] = v;
        }
    }
}

// ------------------------------ BN of X@Wx0, in place ---------------------
// One thread per (t, gate-col): batch mean/var over the 64 rows of that
// timestep, then writes gx0*(x-m)*rsqrt(v+eps) back in place.
__global__ void k_bnx(const float* __restrict__ gx0) {
    int idx = blockIdx.x * 256 + threadIdx.x;   // t*4096 + c, total 524288
    int t = idx >> 12, c = idx & 4095;
    int base = (t * 64) * FH + c;
    float s = 0.f, s2 = 0.f;
#pragma unroll
    for (int b = 0; b < 64; b++) {
        float v = g_GX0[base + b * FH];
        s += v; s2 += v * v;
    }
    float m = s * (1.f / 64.f);
    float var = fmaxf(s2 * (1.f / 64.f) - m * m, 0.f);
    float scl = gx0[c] * rsqrtf(var + 1e-5f);
#pragma unroll
    for (int b = 0; b < 64; b++) {
        g_GX0[base + b * FH] = scl * (g_GX0[base + b * FH] - m);
    }
}

// ------------------------------ layer-0 step ------------------------------
// grid 128 CTAs, 256 threads. CTA owns h-cols [cta*8, cta*8+8) and the four
// corresponding gate column groups. Fuses GEMM (h0@Wh0 slice), batch-norm
// (CTA-local over the 64 batch rows), gates, c-BN, h update.
__global__ void k_step0(int t, const float* __restrict__ Wh0, const float* __restrict__ b0,
                        const float* __restrict__ gh0, const float* __restrict__ gc0,
                        const float* __restrict__ bc0) {
    const int cta = blockIdx.x;
    const int tid = threadIdx.x;
    const int hc0 = cta * 8;
    const float* hin = g_h0[t & 1];
    float* hout = g_h0[(t + 1) & 1];

    __shared__ float As[32][65];        // h tile [k][r]
    __shared__ float Ws[32][32];        // weight tile [k][c]
    __shared__ float Gs[64][33];        // GEMM result [r][c]
    __shared__ float mh[32], sh[32];
    __shared__ float CsS[64][9], OsS[64][9];
    __shared__ float mc[8], scC[8];

    int tx = tid & 15;                  // col pair
    int ty = tid >> 4;                  // row quad (0..15)
    float acc[4][2] = {};

    for (int k0 = 0; k0 < Hn; k0 += 32) {
#pragma unroll
        for (int i = 0; i < 8; i++) {
            int idx = tid + i * 256;    // 0..2047
            int r = idx >> 5, k = idx & 31;
            As[k][r] = hin[r * Hn + k0 + k];
        }
#pragma unroll
        for (int i = 0; i < 4; i++) {
            int idx = tid + i * 256;    // 0..1023
            int k = idx >> 5, c = idx & 31;
            int col = (c >> 3) * Hn + hc0 + (c & 7);
            Ws[k][c] = Wh0[(k0 + k) * FH + col];
        }
        __syncthreads();
#pragma unroll
        for (int k = 0; k < 32; k++) {
            float w0 = Ws[k][tx * 2], w1 = Ws[k][tx * 2 + 1];
#pragma unroll
            for (int i = 0; i < 4; i++) {
                float a = As[k][ty * 4 + i];
                acc[i][0] += a * w0;
                acc[i][1] += a * w1;
            }
        }
        __syncthreads();
    }
#pragma unroll
    for (int i = 0; i < 4; i++) {
        Gs[ty * 4 + i][tx * 2]     = acc[i][0];
        Gs[ty * 4 + i][tx * 2 + 1] = acc[i][1];
    }
    __syncthreads();

    if (tid < 32) {
        float s = 0.f, s2 = 0.f;
#pragma unroll
        for (int r = 0; r < 64; r++) { float v = Gs[r][tid]; s += v; s2 += v * v; }
        float m = s * (1.f / 64.f);
        float var = fmaxf(s2 * (1.f / 64.f) - m * m, 0.f);
        int col = (tid >> 3) * Hn + hc0 + (tid & 7);
        mh[tid] = m;
        sh[tid] = gh0[col] * rsqrtf(var + 1e-5f);
    }
    __syncthreads();

    for (int it = tid; it < 512; it += 256) {
        int r = it & 63, j = it >> 6;
        int colh = hc0 + j;
        int base = (t * 64 + r) * FH;
        float preI = g_GX0[base + colh]          + sh[j]      * (Gs[r][j]      - mh[j])      + b0[colh];
        float preJ = g_GX0[base + Hn + colh]     + sh[8 + j]  * (Gs[r][8 + j]  - mh[8 + j])  + b0[Hn + colh];
        float preF = g_GX0[base + 2 * Hn + colh] + sh[16 + j] * (Gs[r][16 + j] - mh[16 + j]) + b0[2 * Hn + colh];
        float preO = g_GX0[base + 3 * Hn + colh] + sh[24 + j] * (Gs[r][24 + j] - mh[24 + j]) + b0[3 * Hn + colh];
        float cold = g_c0[r * Hn + colh];
        float cnew = sigm(preF + 1.f) * cold + sigm(preI) * tanhf(preJ);
        g_c0[r * Hn + colh] = cnew;
        CsS[r][j] = cnew;
        OsS[r][j] = preO;
    }
    __syncthreads();

    if (tid < 8) {
        float s = 0.f, s2 = 0.f;
#pragma unroll
        for (int r = 0; r < 64; r++) { float v = CsS[r][tid]; s += v; s2 += v * v; }
        float m = s * (1.f / 64.f);
        float var = fmaxf(s2 * (1.f / 64.f) - m * m, 0.f);
        mc[tid] = m;
        scC[tid] = rsqrtf(var + 1e-5f);
    }
    __syncthreads();

    for (int it = tid; it < 512; it += 256) {
        int r = it & 63, j = it >> 6;
        int colh = hc0 + j;
        float cn = gc0[colh] * (CsS[r][j] - mc[j]) * scC[j] + bc0[colh];
        hout[r * Hn + colh] = sigm(OsS[r][j]) * tanhf(cn);
    }
}

// ------------------------------ layer-1 step ------------------------------
// Same structure, two fused GEMMs (h0_new@Wx1 and h1@Wh1), each with its own
// batch-norm, then gates. Writes h1 ping-pong state AND the h1 history in
// output row order.
__global__ void k_step1(int t, const float* __restrict__ Wx1, const float* __restrict__ Wh1,
                        const float* __restrict__ b1, const float* __restrict__ gx1,
                        const float* __restrict__ gh1, const float* __restrict__ gc1,
                        const float* __restrict__ bc1) {
    const int cta = blockIdx.x;
    const int tid = threadIdx.x;
    const int hc0 = cta * 8;
    const float* h0in = g_h0[(t + 1) & 1];   // written by k_step0(t)
    const float* h1in = g_h1[t & 1];
    float* h1out = g_h1[(t + 1) & 1];

    __shared__ float As[32][65];        // h0 tile [k][r]
    __shared__ float Hs[32][65];        // h1 tile [k][r]
    __shared__ float Wa[32][32];        // Wx1 tile
    __shared__ float Wb[32][32];        // Wh1 tile
    __shared__ float GA[64][33], GB[64][33];
    __shared__ float ma[32], sa[32], mb[32], sb[32];
    __shared__ float CsS[64][9], OsS[64][9];
    __shared__ float mc[8], scC[8];

    int tx = tid & 15;
    int ty = tid >> 4;
    float accA[4][2] = {}, accB[4][2] = {};

    for (int k0 = 0; k0 < Hn; k0 += 32) {
#pragma unroll
        for (int i = 0; i < 8; i++) {
            int idx = tid + i * 256;
            int r = idx >> 5, k = idx & 31;
            As[k][r] = h0in[r * Hn + k0 + k];
            Hs[k][r] = h1in[r * Hn + k0 + k];
        }
#pragma unroll
        for (int i = 0; i < 4; i++) {
            int idx = tid + i * 256;
            int k = idx >> 5, c = idx & 31;
            int col = (c >> 3) * Hn + hc0 + (c & 7);
            Wa[k][c] = Wx1[(k0 + k) * FH + col];
            Wb[k][c] = Wh1[(k0 + k) * FH + col];
        }
        __syncthreads();
#pragma unroll
        for (int k = 0; k < 32; k++) {
            float wa0 = Wa[k][tx * 2], wa1 = Wa[k][tx * 2 + 1];
            float wb0 = Wb[k][tx * 2], wb1 = Wb[k][tx * 2 + 1];
#pragma unroll
            for (int i = 0; i < 4; i++) {
                float a = As[k][ty * 4 + i];
                float h = Hs[k][ty * 4 + i];
                accA[i][0] += a * wa0; accA[i][1] += a * wa1;
                accB[i][0] += h * wb0; accB[i][1] += h * wb1;
            }
        }
        __syncthreads();
    }
#pragma unroll
    for (int i = 0; i < 4; i++) {
        GA[ty * 4 + i][tx * 2]     = accA[i][0];
        GA[ty * 4 + i][tx * 2 + 1] = accA[i][1];
        GB[ty * 4 + i][tx * 2]     = accB[i][0];
        GB[ty * 4 + i][tx * 2 + 1] = accB[i][1];
    }
    __syncthreads();

    if (tid < 64) {
        int c = tid & 31, which = tid >> 5;
        float s = 0.f, s2 = 0.f;
        if (which == 0) {
#pragma unroll
            for (int r = 0; r < 64; r++) { float v = GA[r][c]; s += v; s2 += v * v; }
        } else {
#pragma unroll
            for (int r = 0; r < 64; r++) { float v = GB[r][c]; s += v; s2 += v * v; }
        }
        float m = s * (1.f / 64.f);
        float var = fmaxf(s2 * (1.f / 64.f) - m * m, 0.f);
        int col = (c >> 3) * Hn + hc0 + (c & 7);
        if (which == 0) { ma[c] = m; sa[c] = gx1[col] * rsqrtf(var + 1e-5f); }
        else            { mb[c] = m; sb[c] = gh1[col] * rsqrtf(var + 1e-5f); }
    }
    __syncthreads();

    for (int it = tid; it < 512; it += 256) {
        int r = it & 63, j = it >> 6;
        int colh = hc0 + j;
        float preI = sa[j]      * (GA[r][j]      - ma[j])      + sb[j]      * (GB[r][j]      - mb[j])      + b1[colh];
        float preJ = sa[8 + j]  * (GA[r][8 + j]  - ma[8 + j])  + sb[8 + j]  * (GB[r][8 + j]  - mb[8 + j])  + b1[Hn + colh];
        float preF = sa[16 + j] * (GA[r][16 + j] - ma[16 + j]) + sb[16 + j] * (GB[r][16 + j] - mb[16 + j]) + b1[2 * Hn + colh];
        float preO = sa[24 + j] * (GA[r][24 + j] - ma[24 + j]) + sb[24 + j] * (GB[r][24 + j] - mb[24 + j]) + b1[3 * Hn + colh];
        float cold = g_c1[r * Hn + colh];
        float cnew = sigm(preF + 1.f) * cold + sigm(preI) * tanhf(preJ);
        g_c1[r * Hn + colh] = cnew;
        CsS[r][j] = cnew;
        OsS[r][j] = preO;
    }
    __syncthreads();

    if (tid < 8) {
        float s = 0.f, s2 = 0.f;
#pragma unroll
        for (int r = 0; r < 64; r++) { float v = CsS[r][tid]; s += v; s2 += v * v; }
        float m = s * (1.f / 64.f);
        float var = fmaxf(s2 * (1.f / 64.f) - m * m, 0.f);
        mc[tid] = m;
        scC[tid] = rsqrtf(var + 1e-5f);
    }
    __syncthreads();

    for (int it = tid; it < 512; it += 256) {
        int r = it & 63, j = it >> 6;
        int colh = hc0 + j;
        float cn = gc1[colh] * (CsS[r][j] - mc[j]) * scC[j] + bc1[colh];
        float h = sigm(OsS[r][j]) * tanhf(cn);
        h1out[r * Hn + colh] = h;
        g_H1[(r * Tn + t) * Hn + colh] = h;   // output row order (b*T + t)
    }
}

// ------------------------------ launch ------------------------------------
extern "C" void kernel_launch(void* const* d_in, const int* in_sizes, int n_in,
                              void* d_out, int out_size) {
    const int*   inp = (const int*)  d_in[0];
    const float* emb = (const float*)d_in[1];
    const float* Wx0 = (const float*)d_in[2];
    const float* Wh0 = (const float*)d_in[3];
    const float* b0  = (const float*)d_in[4];
    const float* gx0 = (const float*)d_in[5];
    const float* gh0 = (const float*)d_in[6];
    const float* gc0 = (const float*)d_in[7];
    const float* bc0 = (const float*)d_in[8];
    const float* Wx1 = (const float*)d_in[9];
    const float* Wh1 = (const float*)d_in[10];
    const float* b1  = (const float*)d_in[11];
    const float* gx1 = (const float*)d_in[12];
    const float* gh1 = (const float*)d_in[13];
    const float* gc1 = (const float*)d_in[14];
    const float* bc1 = (const float*)d_in[15];
    const float* Wp  = (const float*)d_in[16];
    const float* bp  = (const float*)d_in[17];
    const float* sw  = (const float*)d_in[18];
    const float* sb  = (const float*)d_in[19];
    float* out = (float*)d_out;

    float *pX, *pGX0, *pH1, *pY;
    cudaGetSymbolAddress((void**)&pX,   g_X);
    cudaGetSymbolAddress((void**)&pGX0, g_GX0);
    cudaGetSymbolAddress((void**)&pH1,  g_H1);
    cudaGetSymbolAddress((void**)&pY,   g_Y);

    k_init<<<256, 256>>>();
    k_embed<<<Tn * Bn, 256>>>(inp, emb);

    // GX0 = X @ Wx0   [8192, 4096], K=256
    k_gemm<<<dim3(FH / 64, (Tn * Bn) / 128), 256>>>(pX, Wx0, nullptr, pGX0,
                                                    Tn * Bn, FH, NUn);
    // normalize GX0 in place (per-timestep batch BN, gx0 folded in)
    k_bnx<<<(Tn * FH) / 256, 256>>>(gx0);

    for (int t = 0; t < Tn; t++) {
        k_step0<<<128, 256>>>(t, Wh0, b0, gh0, gc0, bc0);
        k_step1<<<128, 256>>>(t, Wx1, Wh1, b1, gx1, gh1, gc1, bc1);
    }

    // Y = H1 @ Wp + bp   [8192, 256], K=1024
    k_gemm<<<dim3(NUn / 64, (Tn * Bn) / 128), 256>>>(pH1, Wp, bp, pY,
                                                     Tn * Bn, NUn, Hn);
    // logits = Y @ softmax_w + softmax_b   [8192, 8000], K=256
    k_gemm<<<dim3(Vn / 64, (Tn * Bn) / 128), 256>>>(pY, sw, sb, out,
                                                    Tn * Bn, Vn, NUn);
}

// round 4
// speedup vs baseline: 1.6703x; 1.6703x over previous
#include <cuda_runtime.h>
#include <cuda_bf16.h>
#include <cstdint>
#include <math.h>

#define Tn   128
#define Bn   64
#define Hn   1024
#define NUn  256
#define Vn   8000
#define FH   4096

// ------------------------------ device scratch ----------------------------
__device__ float g_X[Tn * Bn * NUn];
__device__ float g_GX0[Tn * Bn * FH];     // BN(x@Wx0) with gx0 folded
__device__ float g_c0[Bn * Hn];
__device__ float g_c1[Bn * Hn];
__device__ float g_H1[Bn * Tn * Hn];      // h1 history, row (b*T+t)
__device__ float g_Y[Bn * Tn * NUn];

// A-fragment-ordered weight images (bf16 hi plane | lo plane per CTA slice)
// L0: 32 CTAs x (64 ktiles x 8 mtiles x 512B) per plane
__device__ __align__(16) unsigned char g_W0f [32 * 524288];
// L1: 64 CTAs x (64 ktiles x 4 mtiles x 512B) per plane
__device__ __align__(16) unsigned char g_W1xf[64 * 262144];
__device__ __align__(16) unsigned char g_W1hf[64 * 262144];
// B-fragment-ordered h states: [parity][hi 128KB | lo 128KB]
__device__ __align__(16) unsigned char g_h0B[2][262144];
__device__ __align__(16) unsigned char g_h1B[2][262144];

__device__ __forceinline__ float sigm(float x) { return __fdividef(1.f, 1.f + __expf(-x)); }

// m16n8k16 row.col bf16 -> f32 accumulate
#define MMA(c, a, b) \
    asm volatile("mma.sync.aligned.m16n8k16.row.col.f32.bf16.bf16.f32 " \
        "{%0,%1,%2,%3},{%4,%5,%6,%7},{%8,%9},{%0,%1,%2,%3};" \
        : "+f"((c)[0]), "+f"((c)[1]), "+f"((c)[2]), "+f"((c)[3]) \
        : "r"((a).x), "r"((a).y), "r"((a).z), "r"((a).w), "r"((b).x), "r"((b).y))

// write one h value into B-fragment-ordered hi/lo planes
__device__ __forceinline__ void write_hfrag(unsigned char* hb, int b, int hc, float h) {
    __nv_bfloat16 hi = __float2bfloat16(h);
    __nv_bfloat16 lo = __float2bfloat16(h - __bfloat162float(hi));
    int kt = hc >> 4, nt = b >> 3, ki = hc & 15, ni = b & 7;
    int ln = ni * 4 + ((ki & 7) >> 1);
    int off = ((kt * 8 + nt) << 8) + ln * 8 + ((ki >> 3) << 2) + ((ki & 1) << 1);
    *(__nv_bfloat16*)(hb + off) = hi;
    *(__nv_bfloat16*)(hb + 131072 + off) = lo;
}

// ------------------------------ init --------------------------------------
__global__ void k_init() {
    int i = blockIdx.x * 256 + threadIdx.x;   // 131072 threads
    if (i < Bn * Hn) { g_c0[i] = 0.f; g_c1[i] = 0.f; }
    ((uint32_t*)g_h0B)[i] = 0u;
    ((uint32_t*)g_h1B)[i] = 0u;
}

// ------------------------------ embedding ---------------------------------
__global__ void k_embed(const int* __restrict__ inp, const float* __restrict__ emb) {
    int bid = blockIdx.x;
    int t = bid >> 6, b = bid & 63;
    int u = threadIdx.x;
    int idx = inp[b * Tn + t];
    g_X[bid * NUn + u] = emb[idx * NUn + u];
}

// ------------------------------ weight prep -------------------------------
// W[k][gatecol] fp32 -> A-fragment order: tile (kt*MT+mt) 512B, thread lane
// holds a0..a3 at lane*16; hi and lo planes.
__global__ void k_prepw(const float* __restrict__ Wh0, const float* __restrict__ Wx1,
                        const float* __restrict__ Wh1) {
    int which = blockIdx.y;
    const float* W = which == 0 ? Wh0 : (which == 1 ? Wx1 : Wh1);
    int idx = blockIdx.x * 256 + threadIdx.x;   // k*4096 + gcol
    int k = idx >> 12, gcol = idx & 4095;
    float wv = W[idx];
    __nv_bfloat16 hi = __float2bfloat16(wv);
    __nv_bfloat16 lo = __float2bfloat16(wv - __bfloat162float(hi));
    int g = gcol >> 10, hc = gcol & 1023;
    unsigned char* base;
    int MT, losz, m;
    if (which == 0) {
        int c = hc >> 5; m = g * 32 + (hc & 31); MT = 8; losz = 262144;
        base = g_W0f + (size_t)c * 524288;
    } else {
        int c = hc >> 4; m = g * 16 + (hc & 15); MT = 4; losz = 131072;
        base = (which == 1 ? g_W1xf : g_W1hf) + (size_t)c * 262144;
    }
    int kt = k >> 4, ki = k & 15, mt = m >> 4, mi = m & 15;
    int lane = (mi & 7) * 4 + ((ki & 7) >> 1);
    int reg  = (mi >> 3) + ((ki >> 3) << 1);
    int off  = ((kt * MT + mt) << 9) + lane * 16 + (reg << 2) + ((ki & 1) << 1);
    *(__nv_bfloat16*)(base + off) = hi;
    *(__nv_bfloat16*)(base + losz + off) = lo;
}

// ------------------------------ fp32 GEMM (+bias) -------------------------
__global__ void k_gemm(const float* __restrict__ A, const float* __restrict__ B,
                       const float* __restrict__ bias, float* __restrict__ C,
                       int M, int N, int K) {
    __shared__ float As[32][129];
    __shared__ float Bs[32][64];
    int tid = threadIdx.x;
    int bm = blockIdx.y * 128, bn = blockIdx.x * 64;
    int tx = tid & 15, ty = tid >> 4;
    float acc[8][4] = {};
    for (int k0 = 0; k0 < K; k0 += 32) {
#pragma unroll
        for (int i = 0; i < 16; i++) {
            int idx = tid + i * 256;
            int m = idx >> 5, k = idx & 31;
            As[k][m] = A[(long)(bm + m) * K + k0 + k];
        }
#pragma unroll
        for (int i = 0; i < 8; i++) {
            int idx = tid + i * 256;
            int k = idx >> 6, n = idx & 63;
            Bs[k][n] = B[(long)(k0 + k) * N + bn + n];
        }
        __syncthreads();
#pragma unroll
        for (int k = 0; k < 32; k++) {
            float b4[4];
#pragma unroll
            for (int j = 0; j < 4; j++) b4[j] = Bs[k][tx * 4 + j];
#pragma unroll
            for (int i = 0; i < 8; i++) {
                float a = As[k][ty * 8 + i];
#pragma unroll
                for (int j = 0; j < 4; j++) acc[i][j] += a * b4[j];
            }
        }
        __syncthreads();
    }
#pragma unroll
    for (int i = 0; i < 8; i++) {
        int m = bm + ty * 8 + i;
#pragma unroll
        for (int j = 0; j < 4; j++) {
            int n = bn + tx * 4 + j;
            C[(long)m * N + n] = acc[i][j] + (bias ? bias[n] : 0.f);
        }
    }
}

// ------------------------------ BN of X@Wx0 -------------------------------
__global__ void k_bnx(const float* __restrict__ gx0) {
    int idx = blockIdx.x * 256 + threadIdx.x;
    int t = idx >> 12, c = idx & 4095;
    int base = (t * 64) * FH + c;
    float s = 0.f, s2 = 0.f;
#pragma unroll
    for (int b = 0; b < 64; b++) {
        float v = g_GX0[base + b * FH];
        s += v; s2 += v * v;
    }
    float m = s * (1.f / 64.f);
    float var = fmaxf(s2 * (1.f / 64.f) - m * m, 0.f);
    float scl = gx0[c] * rsqrtf(var + 1e-5f);
#pragma unroll
    for (int b = 0; b < 64; b++)
        g_GX0[base + b * FH] = scl * (g_GX0[base + b * FH] - m);
}

// ------------------------------ fused step kernel -------------------------
// 96 CTAs x 128 thr. CTAs 0..31: layer0(t). CTAs 32..95: layer1(t-1).
// mma.sync bf16 hi/lo 3-product, fragments LDG'd directly from L2.
__global__ void __launch_bounds__(128) k_step(int t,
        const float* __restrict__ b0,  const float* __restrict__ gh0,
        const float* __restrict__ gc0, const float* __restrict__ bc0,
        const float* __restrict__ b1,  const float* __restrict__ gx1,
        const float* __restrict__ gh1, const float* __restrict__ gc1,
        const float* __restrict__ bc1) {
    __shared__ float Cs[128][65];
    __shared__ float psA[8][32], ps2A[8][32];
    __shared__ float mcA[32], rsA[32];

    const int tid = threadIdx.x, w = tid >> 5, lane = tid & 31;
    const bool isL1 = blockIdx.x >= 32;

    if (!isL1) {
        // ---------------- layer 0, step u=t ----------------
        if (t >= Tn) return;
        const int u = t, c = blockIdx.x;
        const unsigned char* Ah = g_W0f + (size_t)c * 524288;
        const unsigned char* Bh = g_h0B[u & 1];

        float acc[2][8][4] = {};
        uint4 ah[2][2], al[2][2];
        uint2 bh[2][8], bl[2][8];
#pragma unroll
        for (int mt = 0; mt < 2; mt++) {
            size_t o = (size_t)((w * 2 + mt) << 9) + lane * 16;
            ah[0][mt] = *(const uint4*)(Ah + o);
            al[0][mt] = *(const uint4*)(Ah + 262144 + o);
        }
#pragma unroll
        for (int j = 0; j < 8; j++) {
            size_t o = (size_t)(j << 8) + lane * 8;
            bh[0][j] = *(const uint2*)(Bh + o);
            bl[0][j] = *(const uint2*)(Bh + 131072 + o);
        }
#pragma unroll 2
        for (int kt = 0; kt < 64; kt++) {
            int s = kt & 1, n = s ^ 1;
            if (kt < 63) {
#pragma unroll
                for (int mt = 0; mt < 2; mt++) {
                    size_t o = ((size_t)((kt + 1) * 8 + w * 2 + mt) << 9) + lane * 16;
                    ah[n][mt] = *(const uint4*)(Ah + o);
                    al[n][mt] = *(const uint4*)(Ah + 262144 + o);
                }
#pragma unroll
                for (int j = 0; j < 8; j++) {
                    size_t o = ((size_t)((kt + 1) * 8 + j) << 8) + lane * 8;
                    bh[n][j] = *(const uint2*)(Bh + o);
                    bl[n][j] = *(const uint2*)(Bh + 131072 + o);
                }
            }
#pragma unroll
            for (int mt = 0; mt < 2; mt++)
#pragma unroll
                for (int j = 0; j < 8; j++) {
                    MMA(acc[mt][j], ah[s][mt], bh[s][j]);
                    MMA(acc[mt][j], al[s][mt], bh[s][j]);
                    MMA(acc[mt][j], ah[s][mt], bl[s][j]);
                }
        }
        // frags -> SMEM
#pragma unroll
        for (int mt = 0; mt < 2; mt++)
#pragma unroll
            for (int j = 0; j < 8; j++) {
                int r0 = w * 32 + mt * 16 + (lane >> 2);
                int cl = j * 8 + (lane & 3) * 2;
                Cs[r0][cl]     = acc[mt][j][0];
                Cs[r0][cl + 1] = acc[mt][j][1];
                Cs[r0 + 8][cl]     = acc[mt][j][2];
                Cs[r0 + 8][cl + 1] = acc[mt][j][3];
            }
        __syncthreads();

        // per-row (gatecol) BN over batch, gh0 folded
        {
            int r = tid;
            float gam = gh0[(r >> 5) * Hn + c * 32 + (r & 31)];
            float s = 0.f, s2 = 0.f;
#pragma unroll
            for (int b = 0; b < 64; b++) { float v = Cs[r][b]; s += v; s2 += v * v; }
            float m = s * (1.f / 64.f);
            float var = fmaxf(s2 * (1.f / 64.f) - m * m, 0.f);
            float sc = gam * rsqrtf(var + 1e-5f);
#pragma unroll
            for (int b = 0; b < 64; b++) Cs[r][b] = sc * (Cs[r][b] - m);
        }
        __syncthreads();

        // gates + c update
        int hcl = tid & 31, bg = tid >> 5;
        int hc = c * 32 + hcl;
        float cv[16], ov[16], ps = 0.f, p2 = 0.f;
        float bI = b0[hc], bJ = b0[Hn + hc], bF = b0[2 * Hn + hc], bO = b0[3 * Hn + hc];
#pragma unroll
        for (int i = 0; i < 16; i++) {
            int b = bg * 16 + i;
            const float* gx = g_GX0 + (size_t)(u * 64 + b) * FH;
            float preI = Cs[hcl][b]      + gx[hc]          + bI;
            float preJ = Cs[32 + hcl][b] + gx[Hn + hc]     + bJ;
            float preF = Cs[64 + hcl][b] + gx[2 * Hn + hc] + bF;
            float preO = Cs[96 + hcl][b] + gx[3 * Hn + hc] + bO;
            float cold = g_c0[b * Hn + hc];
            float cn = sigm(preF + 1.f) * cold + sigm(preI) * tanhf(preJ);
            g_c0[b * Hn + hc] = cn;
            cv[i] = cn; ov[i] = preO; ps += cn; p2 += cn * cn;
        }
        psA[bg][hcl] = ps; ps2A[bg][hcl] = p2;
        __syncthreads();
        if (tid < 32) {
            float s = psA[0][tid] + psA[1][tid] + psA[2][tid] + psA[3][tid];
            float s2 = ps2A[0][tid] + ps2A[1][tid] + ps2A[2][tid] + ps2A[3][tid];
            float m = s * (1.f / 64.f);
            float var = fmaxf(s2 * (1.f / 64.f) - m * m, 0.f);
            mcA[tid] = m; rsA[tid] = rsqrtf(var + 1e-5f);
        }
        __syncthreads();
        float gcv = gc0[hc], bcv = bc0[hc], mm = mcA[hcl], rr = rsA[hcl];
        unsigned char* hb = g_h0B[(u + 1) & 1];
#pragma unroll
        for (int i = 0; i < 16; i++) {
            float cn = gcv * (cv[i] - mm) * rr + bcv;
            float h = sigm(ov[i]) * tanhf(cn);
            write_hfrag(hb, bg * 16 + i, hc, h);
        }
    } else {
        // ---------------- layer 1, step u=t-1 ----------------
        if (t == 0) return;
        const int u = t - 1, c = (int)blockIdx.x - 32;
        const unsigned char* WA[2] = { g_W1xf + (size_t)c * 262144,
                                       g_W1hf + (size_t)c * 262144 };
        const unsigned char* BB[2] = { g_h0B[(u + 1) & 1], g_h1B[u & 1] };

        float acc[2][8][4] = {};
#pragma unroll 1
        for (int g = 0; g < 2; g++) {
            const unsigned char* Ah = WA[g];
            const unsigned char* Bh = BB[g];
            uint4 ah[2], al[2];
            uint2 bh[2][8], bl[2][8];
            {
                size_t o = (size_t)(w << 9) + lane * 16;
                ah[0] = *(const uint4*)(Ah + o);
                al[0] = *(const uint4*)(Ah + 131072 + o);
#pragma unroll
                for (int j = 0; j < 8; j++) {
                    size_t ob = (size_t)(j << 8) + lane * 8;
                    bh[0][j] = *(const uint2*)(Bh + ob);
                    bl[0][j] = *(const uint2*)(Bh + 131072 + ob);
                }
            }
#pragma unroll 2
            for (int kt = 0; kt < 64; kt++) {
                int s = kt & 1, n = s ^ 1;
                if (kt < 63) {
                    size_t o = ((size_t)((kt + 1) * 4 + w) << 9) + lane * 16;
                    ah[n] = *(const uint4*)(Ah + o);
                    al[n] = *(const uint4*)(Ah + 131072 + o);
#pragma unroll
                    for (int j = 0; j < 8; j++) {
                        size_t ob = ((size_t)((kt + 1) * 8 + j) << 8) + lane * 8;
                        bh[n][j] = *(const uint2*)(Bh + ob);
                        bl[n][j] = *(const uint2*)(Bh + 131072 + ob);
                    }
                }
#pragma unroll
                for (int j = 0; j < 8; j++) {
                    MMA(acc[g][j], ah[s], bh[s][j]);
                    MMA(acc[g][j], al[s], bh[s][j]);
                    MMA(acc[g][j], ah[s], bl[s][j]);
                }
            }
        }
        // frags -> SMEM: GEMM0 rows 0..63, GEMM1 rows 64..127
#pragma unroll
        for (int g = 0; g < 2; g++)
#pragma unroll
            for (int j = 0; j < 8; j++) {
                int r0 = g * 64 + w * 16 + (lane >> 2);
                int cl = j * 8 + (lane & 3) * 2;
                Cs[r0][cl]     = acc[g][j][0];
                Cs[r0][cl + 1] = acc[g][j][1];
                Cs[r0 + 8][cl]     = acc[g][j][2];
                Cs[r0 + 8][cl + 1] = acc[g][j][3];
            }
        __syncthreads();

        // per-row BN (gx1 for rows<64, gh1 for rows>=64)
        {
            int r = tid, rr = r & 63;
            int gcl = (rr >> 4) * Hn + c * 16 + (rr & 15);
            float gam = (r < 64) ? gx1[gcl] : gh1[gcl];
            float s = 0.f, s2 = 0.f;
#pragma unroll
            for (int b = 0; b < 64; b++) { float v = Cs[r][b]; s += v; s2 += v * v; }
            float m = s * (1.f / 64.f);
            float var = fmaxf(s2 * (1.f / 64.f) - m * m, 0.f);
            float sc = gam * rsqrtf(var + 1e-5f);
#pragma unroll
            for (int b = 0; b < 64; b++) Cs[r][b] = sc * (Cs[r][b] - m);
        }
        __syncthreads();

        // gates + c update
        int hcl = tid & 15, bg = tid >> 4;
        int hc = c * 16 + hcl;
        float cv[8], ov[8], ps = 0.f, p2 = 0.f;
        float bI = b1[hc], bJ = b1[Hn + hc], bF = b1[2 * Hn + hc], bO = b1[3 * Hn + hc];
#pragma unroll
        for (int i = 0; i < 8; i++) {
            int b = bg * 8 + i;
            float preI = Cs[hcl][b]      + Cs[64 + hcl][b]      + bI;
            float preJ = Cs[16 + hcl][b] + Cs[80 + hcl][b]      + bJ;
            float preF = Cs[32 + hcl][b] + Cs[96 + hcl][b]      + bF;
            float preO = Cs[48 + hcl][b] + Cs[112 + hcl][b]     + bO;
            float cold = g_c1[b * Hn + hc];
            float cn = sigm(preF + 1.f) * cold + sigm(preI) * tanhf(preJ);
            g_c1[b * Hn + hc] = cn;
            cv[i] = cn; ov[i] = preO; ps += cn; p2 += cn * cn;
        }
        psA[bg][hcl] = ps; ps2A[bg][hcl] = p2;
        __syncthreads();
        if (tid < 16) {
            float s = 0.f, s2 = 0.f;
#pragma unroll
            for (int g = 0; g < 8; g++) { s += psA[g][tid]; s2 += ps2A[g][tid]; }
            float m = s * (1.f / 64.f);
            float var = fmaxf(s2 * (1.f / 64.f) - m * m, 0.f);
            mcA[tid] = m; rsA[tid] = rsqrtf(var + 1e-5f);
        }
        __syncthreads();
        float gcv = gc1[hc], bcv = bc1[hc], mm = mcA[hcl], rr = rsA[hcl];
        unsigned char* hb = g_h1B[(u + 1) & 1];
#pragma unroll
        for (int i = 0; i < 8; i++) {
            int b = bg * 8 + i;
            float cn = gcv * (cv[i] - mm) * rr + bcv;
            float h = sigm(ov[i]) * tanhf(cn);
            write_hfrag(hb, b, hc, h);
            g_H1[((size_t)b * Tn + u) * Hn + hc] = h;
        }
    }
}

// ------------------------------ launch ------------------------------------
extern "C" void kernel_launch(void* const* d_in, const int* in_sizes, int n_in,
                              void* d_out, int out_size) {
    const int*   inp = (const int*)  d_in[0];
    const float* emb = (const float*)d_in[1];
    const float* Wx0 = (const float*)d_in[2];
    const float* Wh0 = (const float*)d_in[3];
    const float* b0  = (const float*)d_in[4];
    const float* gx0 = (const float*)d_in[5];
    const float* gh0 = (const float*)d_in[6];
    const float* gc0 = (const float*)d_in[7];
    const float* bc0 = (const float*)d_in[8];
    const float* Wx1 = (const float*)d_in[9];
    const float* Wh1 = (const float*)d_in[10];
    const float* b1  = (const float*)d_in[11];
    const float* gx1 = (const float*)d_in[12];
    const float* gh1 = (const float*)d_in[13];
    const float* gc1 = (const float*)d_in[14];
    const float* bc1 = (const float*)d_in[15];
    const float* Wp  = (const float*)d_in[16];
    const float* bp  = (const float*)d_in[17];
    const float* sw  = (const float*)d_in[18];
    const float* sb  = (const float*)d_in[19];
    float* out = (float*)d_out;

    float *pX, *pGX0, *pH1, *pY;
    cudaGetSymbolAddress((void**)&pX,   g_X);
    cudaGetSymbolAddress((void**)&pGX0, g_GX0);
    cudaGetSymbolAddress((void**)&pH1,  g_H1);
    cudaGetSymbolAddress((void**)&pY,   g_Y);

    k_init<<<512, 256>>>();
    k_embed<<<Tn * Bn, 256>>>(inp, emb);
    k_prepw<<<dim3(16384, 3), 256>>>(Wh0, Wx1, Wh1);

    // GX0 = X @ Wx0, then per-timestep BN (gx0 folded)
    k_gemm<<<dim3(FH / 64, (Tn * Bn) / 128), 256>>>(pX, Wx0, nullptr, pGX0,
                                                    Tn * Bn, FH, NUn);
    k_bnx<<<(Tn * FH) / 256, 256>>>(gx0);

    for (int t = 0; t <= Tn; t++)
        k_step<<<96, 128>>>(t, b0, gh0, gc0, bc0, b1, gx1, gh1, gc1, bc1);

    k_gemm<<<dim3(NUn / 64, (Tn * Bn) / 128), 256>>>(pH1, Wp, bp, pY,
                                                     Tn * Bn, NUn, Hn);
    k_gemm<<<dim3(Vn / 64, (Tn * Bn) / 128), 256>>>(pY, sw, sb, out,
                                                    Tn * Bn, Vn, NUn);
}

// round 5
// speedup vs baseline: 2.5751x; 1.5417x over previous
#include <cuda_runtime.h>
#include <cuda_bf16.h>
#include <cstdint>
#include <math.h>

#define Tn   128
#define Bn   64
#define Hn   1024
#define NUn  256
#define Vn   8000
#define FH   4096
#define NBLK 96

// ------------------------------ device scratch ----------------------------
__device__ float g_X[Tn * Bn * NUn];
__device__ float g_GX0[Tn * Bn * FH];     // BN(x@Wx0) with gx0 folded
__device__ float g_H1[Bn * Tn * Hn];      // h1 history, row (b*T+t)
__device__ float g_Y[Bn * Tn * NUn];

// A-fragment-ordered weight images (bf16 hi plane | lo plane per CTA slice)
__device__ __align__(16) unsigned char g_W0f [32 * 524288];
__device__ __align__(16) unsigned char g_W1xf[64 * 262144];
__device__ __align__(16) unsigned char g_W1hf[64 * 262144];
// B-fragment-ordered h states: [parity][hi 128KB | lo 128KB]
__device__ __align__(16) unsigned char g_h0B[2][262144];
__device__ __align__(16) unsigned char g_h1B[2][262144];

// grid barrier state
__device__ unsigned g_barCnt;
__device__ volatile unsigned g_barGen;

__device__ __forceinline__ float sigm(float x) { return __fdividef(1.f, 1.f + __expf(-x)); }

#define MMA(c, a, b) \
    asm volatile("mma.sync.aligned.m16n8k16.row.col.f32.bf16.bf16.f32 " \
        "{%0,%1,%2,%3},{%4,%5,%6,%7},{%8,%9},{%0,%1,%2,%3};" \
        : "+f"((c)[0]), "+f"((c)[1]), "+f"((c)[2]), "+f"((c)[3]) \
        : "r"((a).x), "r"((a).y), "r"((a).z), "r"((a).w), "r"((b).x), "r"((b).y))

__device__ __forceinline__ uint32_t smem_u32(const void* p) {
    uint32_t a;
    asm("{ .reg .u64 t; cvta.to.shared.u64 t, %1; cvt.u32.u64 %0, t; }" : "=r"(a) : "l"(p));
    return a;
}
__device__ __forceinline__ void cpa16(uint32_t dst, const void* src) {
    asm volatile("cp.async.cg.shared.global [%0], [%1], 16;" :: "r"(dst), "l"(src) : "memory");
}
#define CP_COMMIT() asm volatile("cp.async.commit_group;" ::: "memory")
#define CP_WAIT(n)  asm volatile("cp.async.wait_group %0;" :: "n"(n) : "memory")

__device__ __forceinline__ void grid_bar() {
    __syncthreads();
    if (threadIdx.x == 0) {
        unsigned gen = g_barGen;
        __threadfence();
        if (atomicAdd(&g_barCnt, 1u) == NBLK - 1) {
            g_barCnt = 0;
            __threadfence();
            g_barGen = gen + 1;
        } else {
            while (g_barGen == gen) { __nanosleep(64); }
        }
        __threadfence();
    }
    __syncthreads();
}

// write one h value into B-fragment-ordered hi/lo planes
__device__ __forceinline__ void write_hfrag(unsigned char* hb, int b, int hc, float h) {
    __nv_bfloat16 hi = __float2bfloat16(h);
    __nv_bfloat16 lo = __float2bfloat16(h - __bfloat162float(hi));
    int kt = hc >> 4, nt = b >> 3, ki = hc & 15, ni = b & 7;
    int ln = ni * 4 + ((ki & 7) >> 1);
    int off = ((kt * 8 + nt) << 8) + ln * 8 + ((ki >> 3) << 2) + ((ki & 1) << 1);
    *(__nv_bfloat16*)(hb + off) = hi;
    *(__nv_bfloat16*)(hb + 131072 + off) = lo;
}

// ------------------------------ init --------------------------------------
__global__ void k_init() {
    int i = blockIdx.x * 256 + threadIdx.x;   // 131072 threads
    ((uint32_t*)g_h0B)[i] = 0u;
    ((uint32_t*)g_h1B)[i] = 0u;
}

// ------------------------------ embedding ---------------------------------
__global__ void k_embed(const int* __restrict__ inp, const float* __restrict__ emb) {
    int bid = blockIdx.x;
    int t = bid >> 6, b = bid & 63;
    int u = threadIdx.x;
    int idx = inp[b * Tn + t];
    g_X[bid * NUn + u] = emb[idx * NUn + u];
}

// ------------------------------ weight prep -------------------------------
__global__ void k_prepw(const float* __restrict__ Wh0, const float* __restrict__ Wx1,
                        const float* __restrict__ Wh1) {
    int which = blockIdx.y;
    const float* W = which == 0 ? Wh0 : (which == 1 ? Wx1 : Wh1);
    int idx = blockIdx.x * 256 + threadIdx.x;   // k*4096 + gcol
    int k = idx >> 12, gcol = idx & 4095;
    float wv = W[idx];
    __nv_bfloat16 hi = __float2bfloat16(wv);
    __nv_bfloat16 lo = __float2bfloat16(wv - __bfloat162float(hi));
    int g = gcol >> 10, hc = gcol & 1023;
    unsigned char* base;
    int MT, losz, m;
    if (which == 0) {
        int c = hc >> 5; m = g * 32 + (hc & 31); MT = 8; losz = 262144;
        base = g_W0f + (size_t)c * 524288;
    } else {
        int c = hc >> 4; m = g * 16 + (hc & 15); MT = 4; losz = 131072;
        base = (which == 1 ? g_W1xf : g_W1hf) + (size_t)c * 262144;
    }
    int kt = k >> 4, ki = k & 15, mt = m >> 4, mi = m & 15;
    int lane = (mi & 7) * 4 + ((ki & 7) >> 1);
    int reg  = (mi >> 3) + ((ki >> 3) << 1);
    int off  = ((kt * MT + mt) << 9) + lane * 16 + (reg << 2) + ((ki & 1) << 1);
    *(__nv_bfloat16*)(base + off) = hi;
    *(__nv_bfloat16*)(base + losz + off) = lo;
}

// ------------------------------ fp32 GEMM (+bias) -------------------------
__global__ void k_gemm(const float* __restrict__ A, const float* __restrict__ B,
                       const float* __restrict__ bias, float* __restrict__ C,
                       int M, int N, int K) {
    __shared__ float As[32][129];
    __shared__ float Bs[32][64];
    int tid = threadIdx.x;
    int bm = blockIdx.y * 128, bn = blockIdx.x * 64;
    int tx = tid & 15, ty = tid >> 4;
    float acc[8][4] = {};
    for (int k0 = 0; k0 < K; k0 += 32) {
#pragma unroll
        for (int i = 0; i < 16; i++) {
            int idx = tid + i * 256;
            int m = idx >> 5, k = idx & 31;
            As[k][m] = A[(long)(bm + m) * K + k0 + k];
        }
#pragma unroll
        for (int i = 0; i < 8; i++) {
            int idx = tid + i * 256;
            int k = idx >> 6, n = idx & 63;
            Bs[k][n] = B[(long)(k0 + k) * N + bn + n];
        }
        __syncthreads();
#pragma unroll
        for (int k = 0; k < 32; k++) {
            float b4[4];
#pragma unroll
            for (int j = 0; j < 4; j++) b4[j] = Bs[k][tx * 4 + j];
#pragma unroll
            for (int i = 0; i < 8; i++) {
                float a = As[k][ty * 8 + i];
#pragma unroll
                for (int j = 0; j < 4; j++) acc[i][j] += a * b4[j];
            }
        }
        __syncthreads();
    }
#pragma unroll
    for (int i = 0; i < 8; i++) {
        int m = bm + ty * 8 + i;
#pragma unroll
        for (int j = 0; j < 4; j++) {
            int n = bn + tx * 4 + j;
            C[(long)m * N + n] = acc[i][j] + (bias ? bias[n] : 0.f);
        }
    }
}

// ------------------------------ BN of X@Wx0 -------------------------------
__global__ void k_bnx(const float* __restrict__ gx0) {
    int idx = blockIdx.x * 256 + threadIdx.x;
    int t = idx >> 12, c = idx & 4095;
    int base = (t * 64) * FH + c;
    float s = 0.f, s2 = 0.f;
#pragma unroll
    for (int b = 0; b < 64; b++) {
        float v = g_GX0[base + b * FH];
        s += v; s2 += v * v;
    }
    float m = s * (1.f / 64.f);
    float var = fmaxf(s2 * (1.f / 64.f) - m * m, 0.f);
    float scl = gx0[c] * rsqrtf(var + 1e-5f);
#pragma unroll
    for (int b = 0; b < 64; b++)
        g_GX0[base + b * FH] = scl * (g_GX0[base + b * FH] - m);
}

// ------------------------------ persistent scan ---------------------------
// 96 CTAs x 256 thr, all 129 steps in one launch, grid barrier per step.
// CTAs 0..31: layer0 (32 hcols each). CTAs 32..95: layer1 (16 hcols each).
// 8 warps: warp-per-mtile (L0) / warp-per-(gemm,mtile) (L1).
// B tiles staged via cp.async.cg (L1-bypass, double-buffered in SMEM).
// c state lives in registers for the whole scan.
__global__ void __launch_bounds__(256) k_scan(
        const float* __restrict__ b0,  const float* __restrict__ gh0,
        const float* __restrict__ gc0, const float* __restrict__ bc0,
        const float* __restrict__ b1,  const float* __restrict__ gx1,
        const float* __restrict__ gh1, const float* __restrict__ gc1,
        const float* __restrict__ bc1) {
    __shared__ __align__(16) unsigned char sm[35584];
    float* fS = (float*)sm;
    float (*Cs)[65] = (float(*)[65])sm;          // epilogue [128][65]
    float* psA  = fS + 8320;                     // 256 floats
    float* ps2A = psA + 256;                     // 256 floats
    float* mcA  = ps2A + 256;                    // 32
    float* rsA  = mcA + 32;                      // 32
    unsigned char* sB = sm;                      // mainloop staging 2x8KB

    const int tid = threadIdx.x, w = tid >> 5, lane = tid & 31;
    const bool isL1 = blockIdx.x >= 32;
    const int c = isL1 ? (int)blockIdx.x - 32 : (int)blockIdx.x;
    const int half = tid >> 7;                   // cp.async: 0=hi plane, 1=lo
    const int off16 = (tid & 127) * 16;

    float creg[8] = {0.f, 0.f, 0.f, 0.f, 0.f, 0.f, 0.f, 0.f};

    for (int t = 0; t <= Tn; t++) {
        if (!isL1) {
            if (t < Tn) {
                const int u = t;
                const unsigned char* Ah = g_W0f + (size_t)c * 524288;
                const unsigned char* Bg = g_h0B[u & 1];
                // prologue: stage B(0)
                cpa16(smem_u32(sB + half * 2048 + off16),
                      Bg + (size_t)half * 131072 + off16);
                CP_COMMIT();
                uint4 ahc = *(const uint4*)(Ah + ((size_t)w << 9) + lane * 16);
                uint4 alc = *(const uint4*)(Ah + 262144 + ((size_t)w << 9) + lane * 16);
                float acc[8][4] = {};
                for (int kt = 0; kt < 64; kt++) {
                    int st = kt & 1;
                    uint4 ahn, aln;
                    if (kt < 63) {
                        size_t gb = (size_t)(kt + 1) << 11;
                        cpa16(smem_u32(sB + (st ^ 1) * 8192 + half * 2048 + off16),
                              Bg + (size_t)half * 131072 + gb + off16);
                        CP_COMMIT();
                        size_t ao = ((size_t)((kt + 1) * 8 + w) << 9) + lane * 16;
                        ahn = *(const uint4*)(Ah + ao);
                        aln = *(const uint4*)(Ah + 262144 + ao);
                        CP_WAIT(1);
                    } else {
                        CP_WAIT(0);
                    }
                    __syncthreads();
                    uint2 bh[8], bl[8];
#pragma unroll
                    for (int j = 0; j < 8; j++) {
                        bh[j] = *(const uint2*)(sB + st * 8192 + (j << 8) + lane * 8);
                        bl[j] = *(const uint2*)(sB + st * 8192 + 2048 + (j << 8) + lane * 8);
                    }
#pragma unroll
                    for (int j = 0; j < 8; j++) {
                        MMA(acc[j], ahc, bh[j]);
                        MMA(acc[j], alc, bh[j]);
                        MMA(acc[j], ahc, bl[j]);
                    }
                    __syncthreads();
                    if (kt < 63) { ahc = ahn; alc = aln; }
                }
                // epilogue
#pragma unroll
                for (int j = 0; j < 8; j++) {
                    int r0 = w * 16 + (lane >> 2);
                    int cl = j * 8 + (lane & 3) * 2;
                    Cs[r0][cl] = acc[j][0]; Cs[r0][cl + 1] = acc[j][1];
                    Cs[r0 + 8][cl] = acc[j][2]; Cs[r0 + 8][cl + 1] = acc[j][3];
                }
                __syncthreads();
                if (tid < 128) {
                    int r = tid;
                    float gam = gh0[(r >> 5) * Hn + c * 32 + (r & 31)];
                    float s = 0.f, s2 = 0.f;
#pragma unroll
                    for (int b = 0; b < 64; b++) { float v = Cs[r][b]; s += v; s2 += v * v; }
                    float m = s * (1.f / 64.f);
                    float var = fmaxf(s2 * (1.f / 64.f) - m * m, 0.f);
                    float sc = gam * rsqrtf(var + 1e-5f);
#pragma unroll
                    for (int b = 0; b < 64; b++) Cs[r][b] = sc * (Cs[r][b] - m);
                }
                __syncthreads();
                int hcl = tid & 31, bg = tid >> 5;
                int hc = c * 32 + hcl;
                float ov[8], ps = 0.f, p2 = 0.f;
                float bI = b0[hc], bJ = b0[Hn + hc], bF = b0[2 * Hn + hc], bO = b0[3 * Hn + hc];
#pragma unroll
                for (int i = 0; i < 8; i++) {
                    int b = bg * 8 + i;
                    const float* gx = g_GX0 + (size_t)(u * 64 + b) * FH;
                    float preI = Cs[hcl][b]      + gx[hc]          + bI;
                    float preJ = Cs[32 + hcl][b] + gx[Hn + hc]     + bJ;
                    float preF = Cs[64 + hcl][b] + gx[2 * Hn + hc] + bF;
                    float preO = Cs[96 + hcl][b] + gx[3 * Hn + hc] + bO;
                    float cn = sigm(preF + 1.f) * creg[i] + sigm(preI) * tanhf(preJ);
                    creg[i] = cn; ov[i] = preO; ps += cn; p2 += cn * cn;
                }
                psA[bg * 32 + hcl] = ps; ps2A[bg * 32 + hcl] = p2;
                __syncthreads();
                if (tid < 32) {
                    float s = 0.f, s2 = 0.f;
#pragma unroll
                    for (int g = 0; g < 8; g++) { s += psA[g * 32 + tid]; s2 += ps2A[g * 32 + tid]; }
                    float m = s * (1.f / 64.f);
                    float var = fmaxf(s2 * (1.f / 64.f) - m * m, 0.f);
                    mcA[tid] = m; rsA[tid] = rsqrtf(var + 1e-5f);
                }
                __syncthreads();
                float gcv = gc0[hc], bcv = bc0[hc], mm = mcA[hcl], rr = rsA[hcl];
                unsigned char* hb = g_h0B[(u + 1) & 1];
#pragma unroll
                for (int i = 0; i < 8; i++) {
                    float cn = gcv * (creg[i] - mm) * rr + bcv;
                    float h = sigm(ov[i]) * tanhf(cn);
                    write_hfrag(hb, bg * 8 + i, hc, h);
                }
            }
        } else {
            if (t >= 1) {
                const int u = t - 1;
                const unsigned char* Ag = (w < 4 ? g_W1xf : g_W1hf) + (size_t)c * 262144;
                const unsigned char* BB0 = g_h0B[(u + 1) & 1];
                const unsigned char* BB1 = g_h1B[u & 1];
                const int g = w >> 2, mt = w & 3;
                const int gsel = g * 4096;
                // prologue: stage both B(0)
                cpa16(smem_u32(sB + half * 2048 + off16), BB0 + (size_t)half * 131072 + off16);
                cpa16(smem_u32(sB + 4096 + half * 2048 + off16), BB1 + (size_t)half * 131072 + off16);
                CP_COMMIT();
                uint4 ahc = *(const uint4*)(Ag + ((size_t)mt << 9) + lane * 16);
                uint4 alc = *(const uint4*)(Ag + 131072 + ((size_t)mt << 9) + lane * 16);
                float acc[8][4] = {};
                for (int kt = 0; kt < 64; kt++) {
                    int st = kt & 1;
                    uint4 ahn, aln;
                    if (kt < 63) {
                        size_t gb = (size_t)(kt + 1) << 11;
                        cpa16(smem_u32(sB + (st ^ 1) * 8192 + half * 2048 + off16),
                              BB0 + (size_t)half * 131072 + gb + off16);
                        cpa16(smem_u32(sB + (st ^ 1) * 8192 + 4096 + half * 2048 + off16),
                              BB1 + (size_t)half * 131072 + gb + off16);
                        CP_COMMIT();
                        size_t ao = ((size_t)((kt + 1) * 4 + mt) << 9) + lane * 16;
                        ahn = *(const uint4*)(Ag + ao);
                        aln = *(const uint4*)(Ag + 131072 + ao);
                        CP_WAIT(1);
                    } else {
                        CP_WAIT(0);
                    }
                    __syncthreads();
                    uint2 bh[8], bl[8];
#pragma unroll
                    for (int j = 0; j < 8; j++) {
                        bh[j] = *(const uint2*)(sB + st * 8192 + gsel + (j << 8) + lane * 8);
                        bl[j] = *(const uint2*)(sB + st * 8192 + gsel + 2048 + (j << 8) + lane * 8);
                    }
#pragma unroll
                    for (int j = 0; j < 8; j++) {
                        MMA(acc[j], ahc, bh[j]);
                        MMA(acc[j], alc, bh[j]);
                        MMA(acc[j], ahc, bl[j]);
                    }
                    __syncthreads();
                    if (kt < 63) { ahc = ahn; alc = aln; }
                }
                // epilogue
#pragma unroll
                for (int j = 0; j < 8; j++) {
                    int r0 = g * 64 + mt * 16 + (lane >> 2);
                    int cl = j * 8 + (lane & 3) * 2;
                    Cs[r0][cl] = acc[j][0]; Cs[r0][cl + 1] = acc[j][1];
                    Cs[r0 + 8][cl] = acc[j][2]; Cs[r0 + 8][cl + 1] = acc[j][3];
                }
                __syncthreads();
                if (tid < 128) {
                    int r = tid, rr = r & 63;
                    int gi = (rr >> 4) * Hn + c * 16 + (rr & 15);
                    float gam = (r < 64) ? gx1[gi] : gh1[gi];
                    float s = 0.f, s2 = 0.f;
#pragma unroll
                    for (int b = 0; b < 64; b++) { float v = Cs[r][b]; s += v; s2 += v * v; }
                    float m = s * (1.f / 64.f);
                    float var = fmaxf(s2 * (1.f / 64.f) - m * m, 0.f);
                    float sc = gam * rsqrtf(var + 1e-5f);
#pragma unroll
                    for (int b = 0; b < 64; b++) Cs[r][b] = sc * (Cs[r][b] - m);
                }
                __syncthreads();
                int hcl = tid & 15, bg = tid >> 4;
                int hc = c * 16 + hcl;
                float ov[4], ps = 0.f, p2 = 0.f;
                float bI = b1[hc], bJ = b1[Hn + hc], bF = b1[2 * Hn + hc], bO = b1[3 * Hn + hc];
#pragma unroll
                for (int i = 0; i < 4; i++) {
                    int b = bg * 4 + i;
                    float preI = Cs[hcl][b]      + Cs[64 + hcl][b]  + bI;
                    float preJ = Cs[16 + hcl][b] + Cs[80 + hcl][b]  + bJ;
                    float preF = Cs[32 + hcl][b] + Cs[96 + hcl][b]  + bF;
                    float preO = Cs[48 + hcl][b] + Cs[112 + hcl][b] + bO;
                    float cn = sigm(preF + 1.f) * creg[i] + sigm(preI) * tanhf(preJ);
                    creg[i] = cn; ov[i] = preO; ps += cn; p2 += cn * cn;
                }
                psA[bg * 16 + hcl] = ps; ps2A[bg * 16 + hcl] = p2;
                __syncthreads();
                if (tid < 16) {
                    float s = 0.f, s2 = 0.f;
#pragma unroll
                    for (int gg = 0; gg < 16; gg++) { s += psA[gg * 16 + tid]; s2 += ps2A[gg * 16 + tid]; }
                    float m = s * (1.f / 64.f);
                    float var = fmaxf(s2 * (1.f / 64.f) - m * m, 0.f);
                    mcA[tid] = m; rsA[tid] = rsqrtf(var + 1e-5f);
                }
                __syncthreads();
                float gcv = gc1[hc], bcv = bc1[hc], mm = mcA[hcl], rr = rsA[hcl];
                unsigned char* hb = g_h1B[(u + 1) & 1];
#pragma unroll
                for (int i = 0; i < 4; i++) {
                    int b = bg * 4 + i;
                    float cn = gcv * (creg[i] - mm) * rr + bcv;
                    float h = sigm(ov[i]) * tanhf(cn);
                    write_hfrag(hb, b, hc, h);
                    g_H1[((size_t)b * Tn + u) * Hn + hc] = h;
                }
            }
        }
        grid_bar();
    }
}

// ------------------------------ launch ------------------------------------
extern "C" void kernel_launch(void* const* d_in, const int* in_sizes, int n_in,
                              void* d_out, int out_size) {
    const int*   inp = (const int*)  d_in[0];
    const float* emb = (const float*)d_in[1];
    const float* Wx0 = (const float*)d_in[2];
    const float* Wh0 = (const float*)d_in[3];
    const float* b0  = (const float*)d_in[4];
    const float* gx0 = (const float*)d_in[5];
    const float* gh0 = (const float*)d_in[6];
    const float* gc0 = (const float*)d_in[7];
    const float* bc0 = (const float*)d_in[8];
    const float* Wx1 = (const float*)d_in[9];
    const float* Wh1 = (const float*)d_in[10];
    const float* b1  = (const float*)d_in[11];
    const float* gx1 = (const float*)d_in[12];
    const float* gh1 = (const float*)d_in[13];
    const float* gc1 = (const float*)d_in[14];
    const float* bc1 = (const float*)d_in[15];
    const float* Wp  = (const float*)d_in[16];
    const float* bp  = (const float*)d_in[17];
    const float* sw  = (const float*)d_in[18];
    const float* sb  = (const float*)d_in[19];
    float* out = (float*)d_out;

    float *pX, *pGX0, *pH1, *pY;
    cudaGetSymbolAddress((void**)&pX,   g_X);
    cudaGetSymbolAddress((void**)&pGX0, g_GX0);
    cudaGetSymbolAddress((void**)&pH1,  g_H1);
    cudaGetSymbolAddress((void**)&pY,   g_Y);

    k_init<<<512, 256>>>();
    k_embed<<<Tn * Bn, 256>>>(inp, emb);
    k_prepw<<<dim3(16384, 3), 256>>>(Wh0, Wx1, Wh1);

    // GX0 = X @ Wx0, then per-timestep BN (gx0 folded)
    k_gemm<<<dim3(FH / 64, (Tn * Bn) / 128), 256>>>(pX, Wx0, nullptr, pGX0,
                                                    Tn * Bn, FH, NUn);
    k_bnx<<<(Tn * FH) / 256, 256>>>(gx0);

    // full recurrent scan in one persistent kernel
    k_scan<<<NBLK, 256>>>(b0, gh0, gc0, bc0, b1, gx1, gh1, gc1, bc1);

    k_gemm<<<dim3(NUn / 64, (Tn * Bn) / 128), 256>>>(pH1, Wp, bp, pY,
                                                     Tn * Bn, NUn, Hn);
    k_gemm<<<dim3(Vn / 64, (Tn * Bn) / 128), 256>>>(pY, sw, sb, out,
                                                    Tn * Bn, Vn, NUn);
}

// round 7
// speedup vs baseline: 3.4014x; 1.3209x over previous
#include <cuda_runtime.h>
#include <cuda_bf16.h>
#include <cstdint>
#include <math.h>

#define Tn   128
#define Bn   64
#define Hn   1024
#define NUn  256
#define Vn   8000
#define FH   4096
#define NBLK 96
#define APLANE 4194304   // 8192*512 bytes: one plane of an A-frag image (M=8192,K=256)

// ------------------------------ device scratch ----------------------------
__device__ float g_GX0[Tn * Bn * FH];     // BN(x@Wx0) with gx0 folded
__device__ float g_H1[Bn * Tn * Hn];      // h1 history, row (b*T+t)
__device__ float g_Y[Bn * Tn * NUn];      // projection output (fp32, exact)

// scan weights: A-fragment images (hi plane | lo plane per CTA slice)
__device__ __align__(16) unsigned char g_W0f [32 * 524288];
__device__ __align__(16) unsigned char g_W1xf[64 * 262144];
__device__ __align__(16) unsigned char g_W1hf[64 * 262144];
// h states as B-fragment images: [parity][hi 128KB | lo 128KB]
__device__ __align__(16) unsigned char g_h0B[2][262144];
__device__ __align__(16) unsigned char g_h1B[2][262144];
// A-frag images of activations (hi|lo planes of 4MB each)
__device__ __align__(16) unsigned char g_Xf[2 * APLANE];
__device__ __align__(16) unsigned char g_Yf[2 * APLANE];
// B-frag images of Wx0 (K=256,N=4096) and softmax_w (K=256,N=8000)
__device__ __align__(16) unsigned char g_Wx0B[2 * 4096 * 512];
__device__ __align__(16) unsigned char g_swB [2 * 8000 * 512];

__device__ unsigned g_barCnt;
__device__ volatile unsigned g_barGen;

__device__ __forceinline__ float sigm(float x) { return __fdividef(1.f, 1.f + __expf(-x)); }

#define MMA(c, a, b) \
    asm volatile("mma.sync.aligned.m16n8k16.row.col.f32.bf16.bf16.f32 " \
        "{%0,%1,%2,%3},{%4,%5,%6,%7},{%8,%9},{%0,%1,%2,%3};" \
        : "+f"((c)[0]), "+f"((c)[1]), "+f"((c)[2]), "+f"((c)[3]) \
        : "r"((a).x), "r"((a).y), "r"((a).z), "r"((a).w), "r"((b).x), "r"((b).y))

__device__ __forceinline__ uint32_t smem_u32(const void* p) {
    uint32_t a;
    asm("{ .reg .u64 t; cvta.to.shared.u64 t, %1; cvt.u32.u64 %0, t; }" : "=r"(a) : "l"(p));
    return a;
}
__device__ __forceinline__ void cpa16(uint32_t dst, const void* src) {
    asm volatile("cp.async.cg.shared.global [%0], [%1], 16;" :: "r"(dst), "l"(src) : "memory");
}
#define CP_COMMIT() asm volatile("cp.async.commit_group;" ::: "memory")
#define CP_WAIT(n)  asm volatile("cp.async.wait_group %0;" :: "n"(n) : "memory")

__device__ __forceinline__ void grid_bar() {
    __syncthreads();
    if (threadIdx.x == 0) {
        unsigned gen = g_barGen;
        __threadfence();
        if (atomicAdd(&g_barCnt, 1u) == NBLK - 1) {
            g_barCnt = 0;
            __threadfence();
            g_barGen = gen + 1;
        } else {
            while (g_barGen == gen) { __nanosleep(64); }
        }
        __threadfence();
    }
    __syncthreads();
}

// A-fragment offset for element (row m, col k) in a K=256 image
__device__ __forceinline__ size_t afrag_off(int m, int k) {
    int mt = m >> 4, mi = m & 15, kt = k >> 4, ki = k & 15;
    int lane = (mi & 7) * 4 + ((ki & 7) >> 1);
    int reg  = (mi >> 3) + ((ki >> 3) << 1);
    return ((size_t)(mt * 16 + kt) << 9) + lane * 16 + (reg << 2) + ((ki & 1) << 1);
}
// B-fragment offset for element (k, col n) in a K=256 image (ntile-major)
__device__ __forceinline__ size_t bfrag_off(int k, int n) {
    int nt = n >> 3, ni = n & 7, kt = k >> 4, ki = k & 15;
    int ln = ni * 4 + ((ki & 7) >> 1);
    return ((size_t)(nt * 16 + kt) << 8) + ln * 8 + ((ki >> 3) << 2) + ((ki & 1) << 1);
}

// write one h value into scan B-frag planes (kt-major tiles, K=1024)
__device__ __forceinline__ void write_hfrag(unsigned char* hb, int b, int hc, float h) {
    __nv_bfloat16 hi = __float2bfloat16(h);
    __nv_bfloat16 lo = __float2bfloat16(h - __bfloat162float(hi));
    int kt = hc >> 4, nt = b >> 3, ki = hc & 15, ni = b & 7;
    int ln = ni * 4 + ((ki & 7) >> 1);
    int off = ((kt * 8 + nt) << 8) + ln * 8 + ((ki >> 3) << 2) + ((ki & 1) << 1);
    *(__nv_bfloat16*)(hb + off) = hi;
    *(__nv_bfloat16*)(hb + 131072 + off) = lo;
}

// ------------------------------ init --------------------------------------
__global__ void k_init() {
    int i = blockIdx.x * 256 + threadIdx.x;   // 131072 threads
    ((uint32_t*)g_h0B)[i] = 0u;
    ((uint32_t*)g_h1B)[i] = 0u;
}

// ------------------------------ embedding -> X A-frags --------------------
__global__ void k_embed(const int* __restrict__ inp, const float* __restrict__ emb) {
    int row = blockIdx.x;                 // t*64 + b
    int u = threadIdx.x;
    int t = row >> 6, b = row & 63;
    float v = emb[(size_t)inp[b * Tn + t] * NUn + u];
    __nv_bfloat16 hi = __float2bfloat16(v);
    __nv_bfloat16 lo = __float2bfloat16(v - __bfloat162float(hi));
    size_t off = afrag_off(row, u);
    *(__nv_bfloat16*)(g_Xf + off) = hi;
    *(__nv_bfloat16*)(g_Xf + APLANE + off) = lo;
}

// ------------------------------ Y fp32 -> A-frags -------------------------
__global__ void k_fragA(const float* __restrict__ Y) {
    int row = blockIdx.x, u = threadIdx.x;
    float v = Y[(size_t)row * NUn + u];
    __nv_bfloat16 hi = __float2bfloat16(v);
    __nv_bfloat16 lo = __float2bfloat16(v - __bfloat162float(hi));
    size_t off = afrag_off(row, u);
    *(__nv_bfloat16*)(g_Yf + off) = hi;
    *(__nv_bfloat16*)(g_Yf + APLANE + off) = lo;
}

// ------------------------------ weight -> B-frags (K=256 GEMMs) -----------
__global__ void k_prepB(const float* __restrict__ W, unsigned char* dst, int N) {
    int idx = blockIdx.x * 256 + threadIdx.x;   // k*N + n
    int k = idx / N, n = idx - k * N;
    float v = W[idx];
    __nv_bfloat16 hi = __float2bfloat16(v);
    __nv_bfloat16 lo = __float2bfloat16(v - __bfloat162float(hi));
    size_t off = bfrag_off(k, n);
    *(__nv_bfloat16*)(dst + off) = hi;
    *(__nv_bfloat16*)(dst + (size_t)N * 512 + off) = lo;
}

// ------------------------------ scan weight prep --------------------------
__global__ void k_prepw(const float* __restrict__ Wh0, const float* __restrict__ Wx1,
                        const float* __restrict__ Wh1) {
    int which = blockIdx.y;
    const float* W = which == 0 ? Wh0 : (which == 1 ? Wx1 : Wh1);
    int idx = blockIdx.x * 256 + threadIdx.x;   // k*4096 + gcol
    int k = idx >> 12, gcol = idx & 4095;
    float wv = W[idx];
    __nv_bfloat16 hi = __float2bfloat16(wv);
    __nv_bfloat16 lo = __float2bfloat16(wv - __bfloat162float(hi));
    int g = gcol >> 10, hc = gcol & 1023;
    unsigned char* base;
    int MT, losz, m;
    if (which == 0) {
        int c = hc >> 5; m = g * 32 + (hc & 31); MT = 8; losz = 262144;
        base = g_W0f + (size_t)c * 524288;
    } else {
        int c = hc >> 4; m = g * 16 + (hc & 15); MT = 4; losz = 131072;
        base = (which == 1 ? g_W1xf : g_W1hf) + (size_t)c * 262144;
    }
    int kt = k >> 4, ki = k & 15, mt = m >> 4, mi = m & 15;
    int lane = (mi & 7) * 4 + ((ki & 7) >> 1);
    int reg  = (mi >> 3) + ((ki >> 3) << 1);
    int off  = ((kt * MT + mt) << 9) + lane * 16 + (reg << 2) + ((ki & 1) << 1);
    *(__nv_bfloat16*)(base + off) = hi;
    *(__nv_bfloat16*)(base + losz + off) = lo;
}

// ------------------------------ MMA GEMM, K=256 ---------------------------
// C[8192, N] = Afrag @ Bfrag (+bias). grid (N/64, 64), 256 thr, 64KB dyn smem.
// SMEM B layout matches the ntile-major image: [nt-local 0..7][kt 0..15]x256B.
__global__ void __launch_bounds__(256) k_gemm_mma(
        const unsigned char* __restrict__ Af, const unsigned char* __restrict__ Bf,
        const float* __restrict__ bias, float* __restrict__ C, int N) {
    extern __shared__ unsigned char sb[];
    const int tid = threadIdx.x, w = tid >> 5, lane = tid & 31;
    const int nb = blockIdx.x, mb = blockIdx.y;
    {
        int p = tid >> 7, o = (tid & 127) * 16;
        const unsigned char* src = Bf + (size_t)p * ((size_t)N * 512) + (size_t)nb * 32768 + o;
        uint32_t dst = smem_u32(sb + p * 32768 + o);
#pragma unroll
        for (int i = 0; i < 16; i++) cpa16(dst + i * 2048, src + i * 2048);
        CP_COMMIT(); CP_WAIT(0);
    }
    __syncthreads();
    const size_t abase = ((size_t)(mb * 8 + w) << 13) + lane * 16;  // (mt*16)*512
    uint4 ahc = *(const uint4*)(Af + abase);
    uint4 alc = *(const uint4*)(Af + APLANE + abase);
    float acc[8][4] = {};
#pragma unroll
    for (int kt = 0; kt < 16; kt++) {
        uint4 ahn, aln;
        if (kt < 15) {
            ahn = *(const uint4*)(Af + abase + (kt + 1) * 512);
            aln = *(const uint4*)(Af + APLANE + abase + (kt + 1) * 512);
        }
        uint2 bh[8], bl[8];
#pragma unroll
        for (int j = 0; j < 8; j++) {
            bh[j] = *(const uint2*)(sb + (j * 16 + kt) * 256 + lane * 8);
            bl[j] = *(const uint2*)(sb + 32768 + (j * 16 + kt) * 256 + lane * 8);
        }
#pragma unroll
        for (int j = 0; j < 8; j++) {
            MMA(acc[j], ahc, bh[j]); MMA(acc[j], alc, bh[j]); MMA(acc[j], ahc, bl[j]);
        }
        ahc = ahn; alc = aln;
    }
    int r0 = mb * 128 + w * 16 + (lane >> 2);
#pragma unroll
    for (int j = 0; j < 8; j++) {
        int col = nb * 64 + j * 8 + (lane & 3) * 2;
        float b0v = bias ? bias[col] : 0.f;
        float b1v = bias ? bias[col + 1] : 0.f;
        *(float2*)(C + (size_t)r0 * N + col) = make_float2(acc[j][0] + b0v, acc[j][1] + b1v);
        *(float2*)(C + (size_t)(r0 + 8) * N + col) = make_float2(acc[j][2] + b0v, acc[j][3] + b1v);
    }
}

// ------------------------------ fp32 GEMM (Wp only) -----------------------
__global__ void k_gemm(const float* __restrict__ A, const float* __restrict__ B,
                       const float* __restrict__ bias, float* __restrict__ C,
                       int M, int N, int K) {
    __shared__ float As[32][129];
    __shared__ float Bs[32][64];
    int tid = threadIdx.x;
    int bm = blockIdx.y * 128, bn = blockIdx.x * 64;
    int tx = tid & 15, ty = tid >> 4;
    float acc[8][4] = {};
    for (int k0 = 0; k0 < K; k0 += 32) {
#pragma unroll
        for (int i = 0; i < 16; i++) {
            int idx = tid + i * 256;
            int m = idx >> 5, k = idx & 31;
            As[k][m] = A[(long)(bm + m) * K + k0 + k];
        }
#pragma unroll
        for (int i = 0; i < 8; i++) {
            int idx = tid + i * 256;
            int k = idx >> 6, n = idx & 63;
            Bs[k][n] = B[(long)(k0 + k) * N + bn + n];
        }
        __syncthreads();
#pragma unroll
        for (int k = 0; k < 32; k++) {
            float b4[4];
#pragma unroll
            for (int j = 0; j < 4; j++) b4[j] = Bs[k][tx * 4 + j];
#pragma unroll
            for (int i = 0; i < 8; i++) {
                float a = As[k][ty * 8 + i];
#pragma unroll
                for (int j = 0; j < 4; j++) acc[i][j] += a * b4[j];
            }
        }
        __syncthreads();
    }
#pragma unroll
    for (int i = 0; i < 8; i++) {
        int m = bm + ty * 8 + i;
#pragma unroll
        for (int j = 0; j < 4; j++) {
            int n = bn + tx * 4 + j;
            C[(long)m * N + n] = acc[i][j] + (bias ? bias[n] : 0.f);
        }
    }
}

// ------------------------------ BN of X@Wx0 -------------------------------
__global__ void k_bnx(const float* __restrict__ gx0) {
    int idx = blockIdx.x * 256 + threadIdx.x;
    int t = idx >> 12, c = idx & 4095;
    int base = (t * 64) * FH + c;
    float s = 0.f, s2 = 0.f;
#pragma unroll
    for (int b = 0; b < 64; b++) {
        float v = g_GX0[base + b * FH];
        s += v; s2 += v * v;
    }
    float m = s * (1.f / 64.f);
    float var = fmaxf(s2 * (1.f / 64.f) - m * m, 0.f);
    float scl = gx0[c] * rsqrtf(var + 1e-5f);
#pragma unroll
    for (int b = 0; b < 64; b++)
        g_GX0[base + b * FH] = scl * (g_GX0[base + b * FH] - m);
}

// ------------------------------ persistent scan ---------------------------
// 96 CTAs x 256 thr. CTAs 0..31: layer0 (32 hcols). CTAs 32..95: layer1 (16).
// B double-buffered in 2x64KB dynamic SMEM, K-chunks of 256 (L0) / 128 (L1).
__global__ void __launch_bounds__(256) k_scan(
        const float* __restrict__ b0,  const float* __restrict__ gh0,
        const float* __restrict__ gc0, const float* __restrict__ bc0,
        const float* __restrict__ b1,  const float* __restrict__ gx1,
        const float* __restrict__ gh1, const float* __restrict__ gc1,
        const float* __restrict__ bc1) {
    extern __shared__ __align__(16) unsigned char sm[];
    float (*Cs)[65] = (float(*)[65])sm;            // epilogue aliases buffers
    float* psA  = (float*)(sm + 131072);           // 256
    float* ps2A = psA + 256;                       // 256
    float* mcA  = ps2A + 256;                      // 32
    float* rsA  = mcA + 32;                        // 32

    const int tid = threadIdx.x, w = tid >> 5, lane = tid & 31;
    const bool isL1 = blockIdx.x >= 32;
    const int c = isL1 ? (int)blockIdx.x - 32 : (int)blockIdx.x;

    float creg[8] = {0.f, 0.f, 0.f, 0.f, 0.f, 0.f, 0.f, 0.f};

    for (int t = 0; t <= Tn; t++) {
        if (!isL1 && t < Tn) {
            const int u = t;
            const unsigned char* Ah = g_W0f + (size_t)c * 524288;
            const unsigned char* Bg = g_h0B[u & 1];
            const int p = tid >> 7, cpo = (tid & 127) * 16;
#pragma unroll
            for (int k0 = 0; k0 < 2; k0++) {
                const unsigned char* src = Bg + (size_t)p * 131072 + k0 * 32768 + cpo;
                uint32_t dst = smem_u32(sm + k0 * 65536 + p * 32768 + cpo);
#pragma unroll
                for (int i = 0; i < 16; i++) cpa16(dst + i * 2048, src + i * 2048);
                CP_COMMIT();
            }
            uint4 ahc = *(const uint4*)(Ah + ((size_t)w << 9) + lane * 16);
            uint4 alc = *(const uint4*)(Ah + 262144 + ((size_t)w << 9) + lane * 16);
            float acc[8][4] = {};
            for (int kt = 0; kt < 64; kt++) {
                int kc = kt >> 4;
                if ((kt & 15) == 0) {
                    if (kc < 3) { CP_WAIT(1); } else { CP_WAIT(0); }
                    __syncthreads();
                }
                uint4 ahn, aln;
                if (kt < 63) {
                    size_t ao = ((size_t)((kt + 1) * 8 + w) << 9) + lane * 16;
                    ahn = *(const uint4*)(Ah + ao);
                    aln = *(const uint4*)(Ah + 262144 + ao);
                }
                const unsigned char* bb = sm + (kc & 1) * 65536 + ((kt & 15) << 11);
                uint2 bh[8], bl[8];
#pragma unroll
                for (int j = 0; j < 8; j++) {
                    bh[j] = *(const uint2*)(bb + (j << 8) + lane * 8);
                    bl[j] = *(const uint2*)(bb + 32768 + (j << 8) + lane * 8);
                }
#pragma unroll
                for (int j = 0; j < 8; j++) {
                    MMA(acc[j], ahc, bh[j]); MMA(acc[j], alc, bh[j]); MMA(acc[j], ahc, bl[j]);
                }
                if ((kt & 15) == 15) {
                    __syncthreads();
                    if (kc + 2 < 4) {
                        const unsigned char* src = Bg + (size_t)p * 131072 + (kc + 2) * 32768 + cpo;
                        uint32_t dst = smem_u32(sm + (kc & 1) * 65536 + p * 32768 + cpo);
#pragma unroll
                        for (int i = 0; i < 16; i++) cpa16(dst + i * 2048, src + i * 2048);
                        CP_COMMIT();
                    }
                }
                ahc = ahn; alc = aln;
            }
            __syncthreads();
            // ---------------- epilogue L0 ----------------
#pragma unroll
            for (int j = 0; j < 8; j++) {
                int r0 = w * 16 + (lane >> 2);
                int cl = j * 8 + (lane & 3) * 2;
                Cs[r0][cl] = acc[j][0]; Cs[r0][cl + 1] = acc[j][1];
                Cs[r0 + 8][cl] = acc[j][2]; Cs[r0 + 8][cl + 1] = acc[j][3];
            }
            __syncthreads();
            if (tid < 128) {
                int r = tid;
                float gam = gh0[(r >> 5) * Hn + c * 32 + (r & 31)];
                float s = 0.f, s2 = 0.f;
#pragma unroll
                for (int b = 0; b < 64; b++) { float v = Cs[r][b]; s += v; s2 += v * v; }
                float m = s * (1.f / 64.f);
                float var = fmaxf(s2 * (1.f / 64.f) - m * m, 0.f);
                float sc = gam * rsqrtf(var + 1e-5f);
#pragma unroll
                for (int b = 0; b < 64; b++) Cs[r][b] = sc * (Cs[r][b] - m);
            }
            __syncthreads();
            int hcl = tid & 31, bg = tid >> 5;
            int hc = c * 32 + hcl;
            float ov[8], ps = 0.f, p2 = 0.f;
            float bI = b0[hc], bJ = b0[Hn + hc], bF = b0[2 * Hn + hc], bO = b0[3 * Hn + hc];
#pragma unroll
            for (int i = 0; i < 8; i++) {
                int b = bg * 8 + i;
                const float* gx = g_GX0 + (size_t)(u * 64 + b) * FH;
                float preI = Cs[hcl][b]      + gx[hc]          + bI;
                float preJ = Cs[32 + hcl][b] + gx[Hn + hc]     + bJ;
                float preF = Cs[64 + hcl][b] + gx[2 * Hn + hc] + bF;
                float preO = Cs[96 + hcl][b] + gx[3 * Hn + hc] + bO;
                float cn = sigm(preF + 1.f) * creg[i] + sigm(preI) * tanhf(preJ);
                creg[i] = cn; ov[i] = preO; ps += cn; p2 += cn * cn;
            }
            psA[bg * 32 + hcl] = ps; ps2A[bg * 32 + hcl] = p2;
            __syncthreads();
            if (tid < 32) {
                float s = 0.f, s2 = 0.f;
#pragma unroll
                for (int g = 0; g < 8; g++) { s += psA[g * 32 + tid]; s2 += ps2A[g * 32 + tid]; }
                float m = s * (1.f / 64.f);
                float var = fmaxf(s2 * (1.f / 64.f) - m * m, 0.f);
                mcA[tid] = m; rsA[tid] = rsqrtf(var + 1e-5f);
            }
            __syncthreads();
            float gcv = gc0[hc], bcv = bc0[hc], mm = mcA[hcl], rr = rsA[hcl];
            unsigned char* hb = g_h0B[(u + 1) & 1];
#pragma unroll
            for (int i = 0; i < 8; i++) {
                float cn = gcv * (creg[i] - mm) * rr + bcv;
                float h = sigm(ov[i]) * tanhf(cn);
                write_hfrag(hb, bg * 8 + i, hc, h);
            }
        } else if (isL1 && t >= 1) {
            const int u = t - 1;
            const unsigned char* Ag = (w < 4 ? g_W1xf : g_W1hf) + (size_t)c * 262144;
            const unsigned char* BB[2] = { g_h0B[(u + 1) & 1], g_h1B[u & 1] };
            const int mt = w & 3, gsel = (w >> 2) * 32768;
            const int seg = tid >> 6, sg = seg >> 1, sp = seg & 1;
            const int cpo = (tid & 63) * 16;
#pragma unroll
            for (int k0 = 0; k0 < 2; k0++) {
                const unsigned char* src = BB[sg] + (size_t)sp * 131072 + k0 * 16384 + cpo;
                uint32_t dst = smem_u32(sm + k0 * 65536 + seg * 16384 + cpo);
#pragma unroll
                for (int i = 0; i < 16; i++) cpa16(dst + i * 1024, src + i * 1024);
                CP_COMMIT();
            }
            uint4 ahc = *(const uint4*)(Ag + ((size_t)mt << 9) + lane * 16);
            uint4 alc = *(const uint4*)(Ag + 131072 + ((size_t)mt << 9) + lane * 16);
            float acc[8][4] = {};
            for (int kt = 0; kt < 64; kt++) {
                int kc = kt >> 3;
                if ((kt & 7) == 0) {
                    if (kc < 7) { CP_WAIT(1); } else { CP_WAIT(0); }
                    __syncthreads();
                }
                uint4 ahn, aln;
                if (kt < 63) {
                    size_t ao = ((size_t)((kt + 1) * 4 + mt) << 9) + lane * 16;
                    ahn = *(const uint4*)(Ag + ao);
                    aln = *(const uint4*)(Ag + 131072 + ao);
                }
                const unsigned char* bb = sm + (kc & 1) * 65536 + gsel + ((kt & 7) << 11);
                uint2 bh[8], bl[8];
#pragma unroll
                for (int j = 0; j < 8; j++) {
                    bh[j] = *(const uint2*)(bb + (j << 8) + lane * 8);
                    bl[j] = *(const uint2*)(bb + 16384 + (j << 8) + lane * 8);
                }
#pragma unroll
                for (int j = 0; j < 8; j++) {
                    MMA(acc[j], ahc, bh[j]); MMA(acc[j], alc, bh[j]); MMA(acc[j], ahc, bl[j]);
                }
                if ((kt & 7) == 7) {
                    __syncthreads();
                    if (kc + 2 < 8) {
                        const unsigned char* src = BB[sg] + (size_t)sp * 131072 + (kc + 2) * 16384 + cpo;
                        uint32_t dst = smem_u32(sm + (kc & 1) * 65536 + seg * 16384 + cpo);
#pragma unroll
                        for (int i = 0; i < 16; i++) cpa16(dst + i * 1024, src + i * 1024);
                        CP_COMMIT();
                    }
                }
                ahc = ahn; alc = aln;
            }
            __syncthreads();
            // ---------------- epilogue L1 ----------------
#pragma unroll
            for (int j = 0; j < 8; j++) {
                int r0 = (w >> 2) * 64 + mt * 16 + (lane >> 2);
                int cl = j * 8 + (lane & 3) * 2;
                Cs[r0][cl] = acc[j][0]; Cs[r0][cl + 1] = acc[j][1];
                Cs[r0 + 8][cl] = acc[j][2]; Cs[r0 + 8][cl + 1] = acc[j][3];
            }
            __syncthreads();
            if (tid < 128) {
                int r = tid, rr = r & 63;
                int gi = (rr >> 4) * Hn + c * 16 + (rr & 15);
                float gam = (r < 64) ? gx1[gi] : gh1[gi];
                float s = 0.f, s2 = 0.f;
#pragma unroll
                for (int b = 0; b < 64; b++) { float v = Cs[r][b]; s += v; s2 += v * v; }
                float m = s * (1.f / 64.f);
                float var = fmaxf(s2 * (1.f / 64.f) - m * m, 0.f);
                float sc = gam * rsqrtf(var + 1e-5f);
#pragma unroll
                for (int b = 0; b < 64; b++) Cs[r][b] = sc * (Cs[r][b] - m);
            }
            __syncthreads();
            int hcl = tid & 15, bg = tid >> 4;
            int hc = c * 16 + hcl;
            float ov[4], ps = 0.f, p2 = 0.f;
            float bI = b1[hc], bJ = b1[Hn + hc], bF = b1[2 * Hn + hc], bO = b1[3 * Hn + hc];
#pragma unroll
            for (int i = 0; i < 4; i++) {
                int b = bg * 4 + i;
                float preI = Cs[hcl][b]      + Cs[64 + hcl][b]  + bI;
                float preJ = Cs[16 + hcl][b] + Cs[80 + hcl][b]  + bJ;
                float preF = Cs[32 + hcl][b] + Cs[96 + hcl][b]  + bF;
                float preO = Cs[48 + hcl][b] + Cs[112 + hcl][b] + bO;
                float cn = sigm(preF + 1.f) * creg[i] + sigm(preI) * tanhf(preJ);
                creg[i] = cn; ov[i] = preO; ps += cn; p2 += cn * cn;
            }
            psA[bg * 16 + hcl] = ps; ps2A[bg * 16 + hcl] = p2;
            __syncthreads();
            if (tid < 16) {
                float s = 0.f, s2 = 0.f;
#pragma unroll
                for (int gg = 0; gg < 16; gg++) { s += psA[gg * 16 + tid]; s2 += ps2A[gg * 16 + tid]; }
                float m = s * (1.f / 64.f);
                float var = fmaxf(s2 * (1.f / 64.f) - m * m, 0.f);
                mcA[tid] = m; rsA[tid] = rsqrtf(var + 1e-5f);
            }
            __syncthreads();
            float gcv = gc1[hc], bcv = bc1[hc], mm = mcA[hcl], rr = rsA[hcl];
            unsigned char* hb = g_h1B[(u + 1) & 1];
#pragma unroll
            for (int i = 0; i < 4; i++) {
                int b = bg * 4 + i;
                float cn = gcv * (creg[i] - mm) * rr + bcv;
                float h = sigm(ov[i]) * tanhf(cn);
                write_hfrag(hb, b, hc, h);
                g_H1[((size_t)b * Tn + u) * Hn + hc] = h;
            }
        }
        grid_bar();
    }
}

// ------------------------------ launch ------------------------------------
extern "C" void kernel_launch(void* const* d_in, const int* in_sizes, int n_in,
                              void* d_out, int out_size) {
    const int*   inp = (const int*)  d_in[0];
    const float* emb = (const float*)d_in[1];
    const float* Wx0 = (const float*)d_in[2];
    const float* Wh0 = (const float*)d_in[3];
    const float* b0  = (const float*)d_in[4];
    const float* gx0 = (const float*)d_in[5];
    const float* gh0 = (const float*)d_in[6];
    const float* gc0 = (const float*)d_in[7];
    const float* bc0 = (const float*)d_in[8];
    const float* Wx1 = (const float*)d_in[9];
    const float* Wh1 = (const float*)d_in[10];
    const float* b1  = (const float*)d_in[11];
    const float* gx1 = (const float*)d_in[12];
    const float* gh1 = (const float*)d_in[13];
    const float* gc1 = (const float*)d_in[14];
    const float* bc1 = (const float*)d_in[15];
    const float* Wp  = (const float*)d_in[16];
    const float* bp  = (const float*)d_in[17];
    const float* sw  = (const float*)d_in[18];
    const float* sb  = (const float*)d_in[19];
    float* out = (float*)d_out;

    float *pGX0, *pH1, *pY;
    unsigned char *pXf, *pYf, *pWx0B, *pswB;
    cudaGetSymbolAddress((void**)&pGX0, g_GX0);
    cudaGetSymbolAddress((void**)&pH1,  g_H1);
    cudaGetSymbolAddress((void**)&pY,   g_Y);
    cudaGetSymbolAddress((void**)&pXf,  g_Xf);
    cudaGetSymbolAddress((void**)&pYf,  g_Yf);
    cudaGetSymbolAddress((void**)&pWx0B, g_Wx0B);
    cudaGetSymbolAddress((void**)&pswB,  g_swB);

    cudaFuncSetAttribute(k_scan, cudaFuncAttributeMaxDynamicSharedMemorySize, 135168);
    cudaFuncSetAttribute(k_gemm_mma, cudaFuncAttributeMaxDynamicSharedMemorySize, 65536);

    k_init<<<512, 256>>>();
    k_embed<<<Tn * Bn, 256>>>(inp, emb);
    k_prepw<<<dim3(16384, 3), 256>>>(Wh0, Wx1, Wh1);
    k_prepB<<<(NUn * FH) / 256, 256>>>(Wx0, pWx0B, FH);
    k_prepB<<<(NUn * Vn) / 256, 256>>>(sw, pswB, Vn);

    // GX0 = X @ Wx0 (bf16-split MMA), then per-timestep BN (gx0 folded)
    k_gemm_mma<<<dim3(FH / 64, 64), 256, 65536>>>(pXf, pWx0B, nullptr, pGX0, FH);
    k_bnx<<<(Tn * FH) / 256, 256>>>(gx0);

    // full recurrent scan, one persistent kernel
    k_scan<<<NBLK, 256, 135168>>>(b0, gh0, gc0, bc0, b1, gx1, gh1, gc1, bc1);

    // Y = H1 @ Wp + bp (fp32, small), then logits = Y @ softmax_w + sb (MMA)
    k_gemm<<<dim3(NUn / 64, (Tn * Bn) / 128), 256>>>(pH1, Wp, bp, pY,
                                                     Tn * Bn, NUn, Hn);
    k_fragA<<<Tn * Bn, 256>>>(pY);
    k_gemm_mma<<<dim3(Vn / 64, 64), 256, 65536>>>(pYf, pswB, sb, out, Vn);
}

// round 8
// speedup vs baseline: 3.5793x; 1.0523x over previous
#include <cuda_runtime.h>
#include <cuda_bf16.h>
#include <cstdint>
#include <math.h>

#define Tn   128
#define Bn   64
#define Hn   1024
#define NUn  256
#define Vn   8000
#define FH   4096
#define NBLK 96
#define APLANE 4194304   // 8192*512 bytes: one plane of an A-frag image (M=8192,K=256)

// ------------------------------ device scratch ----------------------------
__device__ float g_GX0[Tn * Bn * FH];     // BN(x@Wx0) with gx0 folded
__device__ float g_H1[Bn * Tn * Hn];      // h1 history, row (b*T+t)
__device__ float g_Y[Bn * Tn * NUn];      // projection output (fp32, exact)

// scan weights: A-fragment images (hi plane | lo plane per CTA slice)
__device__ __align__(16) unsigned char g_W0f [32 * 524288];
__device__ __align__(16) unsigned char g_W1xf[64 * 262144];
__device__ __align__(16) unsigned char g_W1hf[64 * 262144];
// h states as B-fragment images: [parity][hi 128KB | lo 128KB]
__device__ __align__(16) unsigned char g_h0B[2][262144];
__device__ __align__(16) unsigned char g_h1B[2][262144];
// A-frag images of activations (hi|lo planes of 4MB each)
__device__ __align__(16) unsigned char g_Xf[2 * APLANE];
__device__ __align__(16) unsigned char g_Yf[2 * APLANE];
// B-frag images of Wx0 (K=256,N=4096) and softmax_w (K=256,N=8000)
__device__ __align__(16) unsigned char g_Wx0B[2 * 4096 * 512];
__device__ __align__(16) unsigned char g_swB [2 * 8000 * 512];

__device__ unsigned g_barCnt;
__device__ volatile unsigned g_barGen;

__device__ __forceinline__ float sigm(float x) { return __fdividef(1.f, 1.f + __expf(-x)); }

#define MMA(c, a, b) \
    asm volatile("mma.sync.aligned.m16n8k16.row.col.f32.bf16.bf16.f32 " \
        "{%0,%1,%2,%3},{%4,%5,%6,%7},{%8,%9},{%0,%1,%2,%3};" \
        : "+f"((c)[0]), "+f"((c)[1]), "+f"((c)[2]), "+f"((c)[3]) \
        : "r"((a).x), "r"((a).y), "r"((a).z), "r"((a).w), "r"((b).x), "r"((b).y))

__device__ __forceinline__ uint32_t smem_u32(const void* p) {
    uint32_t a;
    asm("{ .reg .u64 t; cvta.to.shared.u64 t, %1; cvt.u32.u64 %0, t; }" : "=r"(a) : "l"(p));
    return a;
}
__device__ __forceinline__ void cpa16(uint32_t dst, const void* src) {
    asm volatile("cp.async.cg.shared.global [%0], [%1], 16;" :: "r"(dst), "l"(src) : "memory");
}
#define CP_COMMIT() asm volatile("cp.async.commit_group;" ::: "memory")
#define CP_WAIT(n)  asm volatile("cp.async.wait_group %0;" :: "n"(n) : "memory")

__device__ __forceinline__ void grid_bar() {
    __syncthreads();
    if (threadIdx.x == 0) {
        unsigned gen = g_barGen;
        __threadfence();
        if (atomicAdd(&g_barCnt, 1u) == NBLK - 1) {
            g_barCnt = 0;
            __threadfence();
            g_barGen = gen + 1;
        } else {
            while (g_barGen == gen) { __nanosleep(64); }
        }
        __threadfence();
    }
    __syncthreads();
}

// A-fragment offset for element (row m, col k) in a K=256 image
__device__ __forceinline__ size_t afrag_off(int m, int k) {
    int mt = m >> 4, mi = m & 15, kt = k >> 4, ki = k & 15;
    int lane = (mi & 7) * 4 + ((ki & 7) >> 1);
    int reg  = (mi >> 3) + ((ki >> 3) << 1);
    return ((size_t)(mt * 16 + kt) << 9) + lane * 16 + (reg << 2) + ((ki & 1) << 1);
}
// B-fragment offset for element (k, col n) in a K=256 image (ntile-major)
__device__ __forceinline__ size_t bfrag_off(int k, int n) {
    int nt = n >> 3, ni = n & 7, kt = k >> 4, ki = k & 15;
    int ln = ni * 4 + ((ki & 7) >> 1);
    return ((size_t)(nt * 16 + kt) << 8) + ln * 8 + ((ki >> 3) << 2) + ((ki & 1) << 1);
}

// write one h value into scan B-frag planes (kt-major tiles, K=1024)
__device__ __forceinline__ void write_hfrag(unsigned char* hb, int b, int hc, float h) {
    __nv_bfloat16 hi = __float2bfloat16(h);
    __nv_bfloat16 lo = __float2bfloat16(h - __bfloat162float(hi));
    int kt = hc >> 4, nt = b >> 3, ki = hc & 15, ni = b & 7;
    int ln = ni * 4 + ((ki & 7) >> 1);
    int off = ((kt * 8 + nt) << 8) + ln * 8 + ((ki >> 3) << 2) + ((ki & 1) << 1);
    *(__nv_bfloat16*)(hb + off) = hi;
    *(__nv_bfloat16*)(hb + 131072 + off) = lo;
}

// ------------------------------ init --------------------------------------
__global__ void k_init() {
    int i = blockIdx.x * 256 + threadIdx.x;   // 131072 threads
    ((uint32_t*)g_h0B)[i] = 0u;
    ((uint32_t*)g_h1B)[i] = 0u;
}

// ------------------------------ embedding -> X A-frags --------------------
__global__ void k_embed(const int* __restrict__ inp, const float* __restrict__ emb) {
    int row = blockIdx.x;                 // t*64 + b
    int u = threadIdx.x;
    int t = row >> 6, b = row & 63;
    float v = emb[(size_t)inp[b * Tn + t] * NUn + u];
    __nv_bfloat16 hi = __float2bfloat16(v);
    __nv_bfloat16 lo = __float2bfloat16(v - __bfloat162float(hi));
    size_t off = afrag_off(row, u);
    *(__nv_bfloat16*)(g_Xf + off) = hi;
    *(__nv_bfloat16*)(g_Xf + APLANE + off) = lo;
}

// ------------------------------ Y fp32 -> A-frags -------------------------
__global__ void k_fragA(const float* __restrict__ Y) {
    int row = blockIdx.x, u = threadIdx.x;
    float v = Y[(size_t)row * NUn + u];
    __nv_bfloat16 hi = __float2bfloat16(v);
    __nv_bfloat16 lo = __float2bfloat16(v - __bfloat162float(hi));
    size_t off = afrag_off(row, u);
    *(__nv_bfloat16*)(g_Yf + off) = hi;
    *(__nv_bfloat16*)(g_Yf + APLANE + off) = lo;
}

// ------------------------------ weight -> B-frags (K=256 GEMMs) -----------
__global__ void k_prepB(const float* __restrict__ W, unsigned char* dst, int N) {
    int idx = blockIdx.x * 256 + threadIdx.x;   // k*N + n
    int k = idx / N, n = idx - k * N;
    float v = W[idx];
    __nv_bfloat16 hi = __float2bfloat16(v);
    __nv_bfloat16 lo = __float2bfloat16(v - __bfloat162float(hi));
    size_t off = bfrag_off(k, n);
    *(__nv_bfloat16*)(dst + off) = hi;
    *(__nv_bfloat16*)(dst + (size_t)N * 512 + off) = lo;
}

// ------------------------------ scan weight prep --------------------------
__global__ void k_prepw(const float* __restrict__ Wh0, const float* __restrict__ Wx1,
                        const float* __restrict__ Wh1) {
    int which = blockIdx.y;
    const float* W = which == 0 ? Wh0 : (which == 1 ? Wx1 : Wh1);
    int idx = blockIdx.x * 256 + threadIdx.x;   // k*4096 + gcol
    int k = idx >> 12, gcol = idx & 4095;
    float wv = W[idx];
    __nv_bfloat16 hi = __float2bfloat16(wv);
    __nv_bfloat16 lo = __float2bfloat16(wv - __bfloat162float(hi));
    int g = gcol >> 10, hc = gcol & 1023;
    unsigned char* base;
    int MT, losz, m;
    if (which == 0) {
        int c = hc >> 5; m = g * 32 + (hc & 31); MT = 8; losz = 262144;
        base = g_W0f + (size_t)c * 524288;
    } else {
        int c = hc >> 4; m = g * 16 + (hc & 15); MT = 4; losz = 131072;
        base = (which == 1 ? g_W1xf : g_W1hf) + (size_t)c * 262144;
    }
    int kt = k >> 4, ki = k & 15, mt = m >> 4, mi = m & 15;
    int lane = (mi & 7) * 4 + ((ki & 7) >> 1);
    int reg  = (mi >> 3) + ((ki >> 3) << 1);
    int off  = ((kt * MT + mt) << 9) + lane * 16 + (reg << 2) + ((ki & 1) << 1);
    *(__nv_bfloat16*)(base + off) = hi;
    *(__nv_bfloat16*)(base + losz + off) = lo;
}

// ------------------------------ MMA GEMM, K=256 ---------------------------
// C[8192, N] = Afrag @ Bfrag (+bias). grid (N/64, 64), 256 thr, 64KB dyn smem.
// SMEM B layout matches the ntile-major image: [nt-local 0..7][kt 0..15]x256B.
__global__ void __launch_bounds__(256) k_gemm_mma(
        const unsigned char* __restrict__ Af, const unsigned char* __restrict__ Bf,
        const float* __restrict__ bias, float* __restrict__ C, int N) {
    extern __shared__ unsigned char sb[];
    const int tid = threadIdx.x, w = tid >> 5, lane = tid & 31;
    const int nb = blockIdx.x, mb = blockIdx.y;
    {
        int p = tid >> 7, o = (tid & 127) * 16;
        const unsigned char* src = Bf + (size_t)p * ((size_t)N * 512) + (size_t)nb * 32768 + o;
        uint32_t dst = smem_u32(sb + p * 32768 + o);
#pragma unroll
        for (int i = 0; i < 16; i++) cpa16(dst + i * 2048, src + i * 2048);
        CP_COMMIT(); CP_WAIT(0);
    }
    __syncthreads();
    const size_t abase = ((size_t)(mb * 8 + w) << 13) + lane * 16;  // (mt*16)*512
    uint4 ahc = *(const uint4*)(Af + abase);
    uint4 alc = *(const uint4*)(Af + APLANE + abase);
    float acc[8][4] = {};
#pragma unroll
    for (int kt = 0; kt < 16; kt++) {
        uint4 ahn, aln;
        if (kt < 15) {
            ahn = *(const uint4*)(Af + abase + (kt + 1) * 512);
            aln = *(const uint4*)(Af + APLANE + abase + (kt + 1) * 512);
        }
        uint2 bh[8], bl[8];
#pragma unroll
        for (int j = 0; j < 8; j++) {
            bh[j] = *(const uint2*)(sb + (j * 16 + kt) * 256 + lane * 8);
            bl[j] = *(const uint2*)(sb + 32768 + (j * 16 + kt) * 256 + lane * 8);
        }
#pragma unroll
        for (int j = 0; j < 8; j++) MMA(acc[j], ahc, bh[j]);
#pragma unroll
        for (int j = 0; j < 8; j++) MMA(acc[j], alc, bh[j]);
#pragma unroll
        for (int j = 0; j < 8; j++) MMA(acc[j], ahc, bl[j]);
        ahc = ahn; alc = aln;
    }
    int r0 = mb * 128 + w * 16 + (lane >> 2);
#pragma unroll
    for (int j = 0; j < 8; j++) {
        int col = nb * 64 + j * 8 + (lane & 3) * 2;
        float b0v = bias ? bias[col] : 0.f;
        float b1v = bias ? bias[col + 1] : 0.f;
        *(float2*)(C + (size_t)r0 * N + col) = make_float2(acc[j][0] + b0v, acc[j][1] + b1v);
        *(float2*)(C + (size_t)(r0 + 8) * N + col) = make_float2(acc[j][2] + b0v, acc[j][3] + b1v);
    }
}

// ------------------------------ fp32 GEMM (Wp only) -----------------------
__global__ void k_gemm(const float* __restrict__ A, const float* __restrict__ B,
                       const float* __restrict__ bias, float* __restrict__ C,
                       int M, int N, int K) {
    __shared__ float As[32][129];
    __shared__ float Bs[32][64];
    int tid = threadIdx.x;
    int bm = blockIdx.y * 128, bn = blockIdx.x * 64;
    int tx = tid & 15, ty = tid >> 4;
    float acc[8][4] = {};
    for (int k0 = 0; k0 < K; k0 += 32) {
#pragma unroll
        for (int i = 0; i < 16; i++) {
            int idx = tid + i * 256;
            int m = idx >> 5, k = idx & 31;
            As[k][m] = A[(long)(bm + m) * K + k0 + k];
        }
#pragma unroll
        for (int i = 0; i < 8; i++) {
            int idx = tid + i * 256;
            int k = idx >> 6, n = idx & 63;
            Bs[k][n] = B[(long)(k0 + k) * N + bn + n];
        }
        __syncthreads();
#pragma unroll
        for (int k = 0; k < 32; k++) {
            float b4[4];
#pragma unroll
            for (int j = 0; j < 4; j++) b4[j] = Bs[k][tx * 4 + j];
#pragma unroll
            for (int i = 0; i < 8; i++) {
                float a = As[k][ty * 8 + i];
#pragma unroll
                for (int j = 0; j < 4; j++) acc[i][j] += a * b4[j];
            }
        }
        __syncthreads();
    }
#pragma unroll
    for (int i = 0; i < 8; i++) {
        int m = bm + ty * 8 + i;
#pragma unroll
        for (int j = 0; j < 4; j++) {
            int n = bn + tx * 4 + j;
            C[(long)m * N + n] = acc[i][j] + (bias ? bias[n] : 0.f);
        }
    }
}

// ------------------------------ BN of X@Wx0 -------------------------------
__global__ void k_bnx(const float* __restrict__ gx0) {
    int idx = blockIdx.x * 256 + threadIdx.x;
    int t = idx >> 12, c = idx & 4095;
    int base = (t * 64) * FH + c;
    float s = 0.f, s2 = 0.f;
#pragma unroll
    for (int b = 0; b < 64; b++) {
        float v = g_GX0[base + b * FH];
        s += v; s2 += v * v;
    }
    float m = s * (1.f / 64.f);
    float var = fmaxf(s2 * (1.f / 64.f) - m * m, 0.f);
    float scl = gx0[c] * rsqrtf(var + 1e-5f);
#pragma unroll
    for (int b = 0; b < 64; b++)
        g_GX0[base + b * FH] = scl * (g_GX0[base + b * FH] - m);
}

// ------------------------------ persistent scan ---------------------------
// 96 CTAs x 512 thr (16 warps). CTAs 0..31: layer0 (32 hcols). CTAs 32..95:
// layer1 (16 hcols). Warp = (mtile, N-half) [L0] / (gemm, mtile, N-half) [L1].
// B double-buffered in 2x64KB dyn SMEM; c state in registers.
__global__ void __launch_bounds__(512) k_scan(
        const float* __restrict__ b0,  const float* __restrict__ gh0,
        const float* __restrict__ gc0, const float* __restrict__ bc0,
        const float* __restrict__ b1,  const float* __restrict__ gx1,
        const float* __restrict__ gh1, const float* __restrict__ gc1,
        const float* __restrict__ bc1) {
    extern __shared__ __align__(16) unsigned char sm[];
    float (*Cs)[65] = (float(*)[65])sm;            // epilogue aliases buffers
    float* psA  = (float*)(sm + 131072);           // 512
    float* ps2A = psA + 512;                       // 512
    float* mcA  = ps2A + 512;                      // 32
    float* rsA  = mcA + 32;                        // 32

    const int tid = threadIdx.x, wid = tid >> 5, lane = tid & 31;
    const bool isL1 = blockIdx.x >= 32;
    const int c = isL1 ? (int)blockIdx.x - 32 : (int)blockIdx.x;

    float creg[4] = {0.f, 0.f, 0.f, 0.f};

    for (int t = 0; t <= Tn; t++) {
        if (!isL1 && t < Tn) {
            const int u = t;
            const unsigned char* Ah = g_W0f + (size_t)c * 524288;
            const unsigned char* Bg = g_h0B[u & 1];
            const int mt = wid & 7, nh = wid >> 3;           // warp role
            const int p = tid >> 8, cpo = (tid & 255) * 16;  // staging role
#pragma unroll
            for (int k0 = 0; k0 < 2; k0++) {
                const unsigned char* src = Bg + (size_t)p * 131072 + k0 * 32768 + cpo;
                uint32_t dst = smem_u32(sm + k0 * 65536 + p * 32768 + cpo);
#pragma unroll
                for (int i = 0; i < 8; i++) cpa16(dst + i * 4096, src + i * 4096);
                CP_COMMIT();
            }
            uint4 ahc = *(const uint4*)(Ah + ((size_t)mt << 9) + lane * 16);
            uint4 alc = *(const uint4*)(Ah + 262144 + ((size_t)mt << 9) + lane * 16);
            float acc[4][4] = {};
            for (int kt = 0; kt < 64; kt++) {
                int kc = kt >> 4;
                if ((kt & 15) == 0) {
                    if (kc < 3) { CP_WAIT(1); } else { CP_WAIT(0); }
                    __syncthreads();
                }
                uint4 ahn, aln;
                if (kt < 63) {
                    size_t ao = ((size_t)((kt + 1) * 8 + mt) << 9) + lane * 16;
                    ahn = *(const uint4*)(Ah + ao);
                    aln = *(const uint4*)(Ah + 262144 + ao);
                }
                const unsigned char* bb = sm + (kc & 1) * 65536 + ((kt & 15) << 11) + (nh << 10);
                uint2 bh[4], bl[4];
#pragma unroll
                for (int j = 0; j < 4; j++) {
                    bh[j] = *(const uint2*)(bb + (j << 8) + lane * 8);
                    bl[j] = *(const uint2*)(bb + 32768 + (j << 8) + lane * 8);
                }
#pragma unroll
                for (int j = 0; j < 4; j++) MMA(acc[j], ahc, bh[j]);
#pragma unroll
                for (int j = 0; j < 4; j++) MMA(acc[j], alc, bh[j]);
#pragma unroll
                for (int j = 0; j < 4; j++) MMA(acc[j], ahc, bl[j]);
                if ((kt & 15) == 15) {
                    __syncthreads();
                    if (kc + 2 < 4) {
                        const unsigned char* src = Bg + (size_t)p * 131072 + (kc + 2) * 32768 + cpo;
                        uint32_t dst = smem_u32(sm + (kc & 1) * 65536 + p * 32768 + cpo);
#pragma unroll
                        for (int i = 0; i < 8; i++) cpa16(dst + i * 4096, src + i * 4096);
                        CP_COMMIT();
                    }
                }
                ahc = ahn; alc = aln;
            }
            __syncthreads();
            // ---------------- epilogue L0 ----------------
#pragma unroll
            for (int j = 0; j < 4; j++) {
                int r0 = mt * 16 + (lane >> 2);
                int cl = (nh * 4 + j) * 8 + (lane & 3) * 2;
                Cs[r0][cl] = acc[j][0]; Cs[r0][cl + 1] = acc[j][1];
                Cs[r0 + 8][cl] = acc[j][2]; Cs[r0 + 8][cl + 1] = acc[j][3];
            }
            __syncthreads();
            {   // BN row pass: 4 threads per row
                int r = tid >> 2, q = tid & 3;
                float s = 0.f, s2 = 0.f;
#pragma unroll
                for (int i = 0; i < 16; i++) {
                    float v = Cs[r][q * 16 + i]; s += v; s2 += v * v;
                }
                s  += __shfl_xor_sync(0xffffffffu, s, 1);
                s  += __shfl_xor_sync(0xffffffffu, s, 2);
                s2 += __shfl_xor_sync(0xffffffffu, s2, 1);
                s2 += __shfl_xor_sync(0xffffffffu, s2, 2);
                float m = s * (1.f / 64.f);
                float var = fmaxf(s2 * (1.f / 64.f) - m * m, 0.f);
                float gam = gh0[(r >> 5) * Hn + c * 32 + (r & 31)];
                float sc = gam * rsqrtf(var + 1e-5f);
#pragma unroll
                for (int i = 0; i < 16; i++)
                    Cs[r][q * 16 + i] = sc * (Cs[r][q * 16 + i] - m);
            }
            __syncthreads();
            int hcl = tid & 31, bg = tid >> 5;     // 16 b-groups of 4
            int hc = c * 32 + hcl;
            float ov[4], ps = 0.f, p2 = 0.f;
            float bI = b0[hc], bJ = b0[Hn + hc], bF = b0[2 * Hn + hc], bO = b0[3 * Hn + hc];
#pragma unroll
            for (int i = 0; i < 4; i++) {
                int b = bg * 4 + i;
                const float* gx = g_GX0 + (size_t)(u * 64 + b) * FH;
                float preI = Cs[hcl][b]      + gx[hc]          + bI;
                float preJ = Cs[32 + hcl][b] + gx[Hn + hc]     + bJ;
                float preF = Cs[64 + hcl][b] + gx[2 * Hn + hc] + bF;
                float preO = Cs[96 + hcl][b] + gx[3 * Hn + hc] + bO;
                float cn = sigm(preF + 1.f) * creg[i] + sigm(preI) * tanhf(preJ);
                creg[i] = cn; ov[i] = preO; ps += cn; p2 += cn * cn;
            }
            psA[bg * 32 + hcl] = ps; ps2A[bg * 32 + hcl] = p2;
            __syncthreads();
            if (tid < 32) {
                float s = 0.f, s2 = 0.f;
#pragma unroll
                for (int g = 0; g < 16; g++) { s += psA[g * 32 + tid]; s2 += ps2A[g * 32 + tid]; }
                float m = s * (1.f / 64.f);
                float var = fmaxf(s2 * (1.f / 64.f) - m * m, 0.f);
                mcA[tid] = m; rsA[tid] = rsqrtf(var + 1e-5f);
            }
            __syncthreads();
            float gcv = gc0[hc], bcv = bc0[hc], mm = mcA[hcl], rr = rsA[hcl];
            unsigned char* hb = g_h0B[(u + 1) & 1];
#pragma unroll
            for (int i = 0; i < 4; i++) {
                float cn = gcv * (creg[i] - mm) * rr + bcv;
                float h = sigm(ov[i]) * tanhf(cn);
                write_hfrag(hb, bg * 4 + i, hc, h);
            }
        } else if (isL1 && t >= 1) {
            const int u = t - 1;
            const int g = wid >> 3, mt = (wid >> 1) & 3, nh = wid & 1;
            const unsigned char* Ag = (g == 0 ? g_W1xf : g_W1hf) + (size_t)c * 262144;
            const unsigned char* BB[2] = { g_h0B[(u + 1) & 1], g_h1B[u & 1] };
            const int gsel = g * 32768;
            const int seg = tid >> 7, sg = seg >> 1, sp = seg & 1;
            const int cpo = (tid & 127) * 16;
#pragma unroll
            for (int k0 = 0; k0 < 2; k0++) {
                const unsigned char* src = BB[sg] + (size_t)sp * 131072 + k0 * 16384 + cpo;
                uint32_t dst = smem_u32(sm + k0 * 65536 + seg * 16384 + cpo);
#pragma unroll
                for (int i = 0; i < 8; i++) cpa16(dst + i * 2048, src + i * 2048);
                CP_COMMIT();
            }
            uint4 ahc = *(const uint4*)(Ag + ((size_t)mt << 9) + lane * 16);
            uint4 alc = *(const uint4*)(Ag + 131072 + ((size_t)mt << 9) + lane * 16);
            float acc[4][4] = {};
            for (int kt = 0; kt < 64; kt++) {
                int kc = kt >> 3;
                if ((kt & 7) == 0) {
                    if (kc < 7) { CP_WAIT(1); } else { CP_WAIT(0); }
                    __syncthreads();
                }
                uint4 ahn, aln;
                if (kt < 63) {
                    size_t ao = ((size_t)((kt + 1) * 4 + mt) << 9) + lane * 16;
                    ahn = *(const uint4*)(Ag + ao);
                    aln = *(const uint4*)(Ag + 131072 + ao);
                }
                const unsigned char* bb = sm + (kc & 1) * 65536 + gsel + ((kt & 7) << 11) + (nh << 10);
                uint2 bh[4], bl[4];
#pragma unroll
                for (int j = 0; j < 4; j++) {
                    bh[j] = *(const uint2*)(bb + (j << 8) + lane * 8);
                    bl[j] = *(const uint2*)(bb + 16384 + (j << 8) + lane * 8);
                }
#pragma unroll
                for (int j = 0; j < 4; j++) MMA(acc[j], ahc, bh[j]);
#pragma unroll
                for (int j = 0; j < 4; j++) MMA(acc[j], alc, bh[j]);
#pragma unroll
                for (int j = 0; j < 4; j++) MMA(acc[j], ahc, bl[j]);
                if ((kt & 7) == 7) {
                    __syncthreads();
                    if (kc + 2 < 8) {
                        const unsigned char* src = BB[sg] + (size_t)sp * 131072 + (kc + 2) * 16384 + cpo;
                        uint32_t dst = smem_u32(sm + (kc & 1) * 65536 + seg * 16384 + cpo);
#pragma unroll
                        for (int i = 0; i < 8; i++) cpa16(dst + i * 2048, src + i * 2048);
                        CP_COMMIT();
                    }
                }
                ahc = ahn; alc = aln;
            }
            __syncthreads();
            // ---------------- epilogue L1 ----------------
#pragma unroll
            for (int j = 0; j < 4; j++) {
                int r0 = g * 64 + mt * 16 + (lane >> 2);
                int cl = (nh * 4 + j) * 8 + (lane & 3) * 2;
                Cs[r0][cl] = acc[j][0]; Cs[r0][cl + 1] = acc[j][1];
                Cs[r0 + 8][cl] = acc[j][2]; Cs[r0 + 8][cl + 1] = acc[j][3];
            }
            __syncthreads();
            {   // BN row pass: 4 threads per row
                int r = tid >> 2, q = tid & 3, rr = r & 63;
                float s = 0.f, s2 = 0.f;
#pragma unroll
                for (int i = 0; i < 16; i++) {
                    float v = Cs[r][q * 16 + i]; s += v; s2 += v * v;
                }
                s  += __shfl_xor_sync(0xffffffffu, s, 1);
                s  += __shfl_xor_sync(0xffffffffu, s, 2);
                s2 += __shfl_xor_sync(0xffffffffu, s2, 1);
                s2 += __shfl_xor_sync(0xffffffffu, s2, 2);
                float m = s * (1.f / 64.f);
                float var = fmaxf(s2 * (1.f / 64.f) - m * m, 0.f);
                int gi = (rr >> 4) * Hn + c * 16 + (rr & 15);
                float gam = (r < 64) ? gx1[gi] : gh1[gi];
                float sc = gam * rsqrtf(var + 1e-5f);
#pragma unroll
                for (int i = 0; i < 16; i++)
                    Cs[r][q * 16 + i] = sc * (Cs[r][q * 16 + i] - m);
            }
            __syncthreads();
            int hcl = tid & 15, bg = tid >> 4;     // 32 b-groups of 2
            int hc = c * 16 + hcl;
            float ov[2], ps = 0.f, p2 = 0.f;
            float bI = b1[hc], bJ = b1[Hn + hc], bF = b1[2 * Hn + hc], bO = b1[3 * Hn + hc];
#pragma unroll
            for (int i = 0; i < 2; i++) {
                int b = bg * 2 + i;
                float preI = Cs[hcl][b]      + Cs[64 + hcl][b]  + bI;
                float preJ = Cs[16 + hcl][b] + Cs[80 + hcl][b]  + bJ;
                float preF = Cs[32 + hcl][b] + Cs[96 + hcl][b]  + bF;
                float preO = Cs[48 + hcl][b] + Cs[112 + hcl][b] + bO;
                float cn = sigm(preF + 1.f) * creg[i] + sigm(preI) * tanhf(preJ);
                creg[i] = cn; ov[i] = preO; ps += cn; p2 += cn * cn;
            }
            psA[bg * 16 + hcl] = ps; ps2A[bg * 16 + hcl] = p2;
            __syncthreads();
            if (tid < 16) {
                float s = 0.f, s2 = 0.f;
#pragma unroll
                for (int gg = 0; gg < 32; gg++) { s += psA[gg * 16 + tid]; s2 += ps2A[gg * 16 + tid]; }
                float m = s * (1.f / 64.f);
                float var = fmaxf(s2 * (1.f / 64.f) - m * m, 0.f);
                mcA[tid] = m; rsA[tid] = rsqrtf(var + 1e-5f);
            }
            __syncthreads();
            float gcv = gc1[hc], bcv = bc1[hc], mm = mcA[hcl], rr = rsA[hcl];
            unsigned char* hb = g_h1B[(u + 1) & 1];
#pragma unroll
            for (int i = 0; i < 2; i++) {
                int b = bg * 2 + i;
                float cn = gcv * (creg[i] - mm) * rr + bcv;
                float h = sigm(ov[i]) * tanhf(cn);
                write_hfrag(hb, b, hc, h);
                g_H1[((size_t)b * Tn + u) * Hn + hc] = h;
            }
        }
        grid_bar();
    }
}

// ------------------------------ launch ------------------------------------
extern "C" void kernel_launch(void* const* d_in, const int* in_sizes, int n_in,
                              void* d_out, int out_size) {
    const int*   inp = (const int*)  d_in[0];
    const float* emb = (const float*)d_in[1];
    const float* Wx0 = (const float*)d_in[2];
    const float* Wh0 = (const float*)d_in[3];
    const float* b0  = (const float*)d_in[4];
    const float* gx0 = (const float*)d_in[5];
    const float* gh0 = (const float*)d_in[6];
    const float* gc0 = (const float*)d_in[7];
    const float* bc0 = (const float*)d_in[8];
    const float* Wx1 = (const float*)d_in[9];
    const float* Wh1 = (const float*)d_in[10];
    const float* b1  = (const float*)d_in[11];
    const float* gx1 = (const float*)d_in[12];
    const float* gh1 = (const float*)d_in[13];
    const float* gc1 = (const float*)d_in[14];
    const float* bc1 = (const float*)d_in[15];
    const float* Wp  = (const float*)d_in[16];
    const float* bp  = (const float*)d_in[17];
    const float* sw  = (const float*)d_in[18];
    const float* sb  = (const float*)d_in[19];
    float* out = (float*)d_out;

    float *pGX0, *pH1, *pY;
    unsigned char *pXf, *pYf, *pWx0B, *pswB;
    cudaGetSymbolAddress((void**)&pGX0, g_GX0);
    cudaGetSymbolAddress((void**)&pH1,  g_H1);
    cudaGetSymbolAddress((void**)&pY,   g_Y);
    cudaGetSymbolAddress((void**)&pXf,  g_Xf);
    cudaGetSymbolAddress((void**)&pYf,  g_Yf);
    cudaGetSymbolAddress((void**)&pWx0B, g_Wx0B);
    cudaGetSymbolAddress((void**)&pswB,  g_swB);

    cudaFuncSetAttribute(k_scan, cudaFuncAttributeMaxDynamicSharedMemorySize, 136192);
    cudaFuncSetAttribute(k_gemm_mma, cudaFuncAttributeMaxDynamicSharedMemorySize, 65536);

    k_init<<<512, 256>>>();
    k_embed<<<Tn * Bn, 256>>>(inp, emb);
    k_prepw<<<dim3(16384, 3), 256>>>(Wh0, Wx1, Wh1);
    k_prepB<<<(NUn * FH) / 256, 256>>>(Wx0, pWx0B, FH);
    k_prepB<<<(NUn * Vn) / 256, 256>>>(sw, pswB, Vn);

    // GX0 = X @ Wx0 (bf16-split MMA), then per-timestep BN (gx0 folded)
    k_gemm_mma<<<dim3(FH / 64, 64), 256, 65536>>>(pXf, pWx0B, nullptr, pGX0, FH);
    k_bnx<<<(Tn * FH) / 256, 256>>>(gx0);

    // full recurrent scan, one persistent kernel
    k_scan<<<NBLK, 512, 136192>>>(b0, gh0, gc0, bc0, b1, gx1, gh1, gc1, bc1);

    // Y = H1 @ Wp + bp (fp32, small), then logits = Y @ softmax_w + sb (MMA)
    k_gemm<<<dim3(NUn / 64, (Tn * Bn) / 128), 256>>>(pH1, Wp, bp, pY,
                                                     Tn * Bn, NUn, Hn);
    k_fragA<<<Tn * Bn, 256>>>(pY);
    k_gemm_mma<<<dim3(Vn / 64, 64), 256, 65536>>>(pYf, pswB, sb, out, Vn);
}

// round 9
// speedup vs baseline: 4.3962x; 1.2282x over previous
#include <cuda_runtime.h>
#include <cuda_bf16.h>
#include <cuda_fp16.h>
#include <cstdint>
#include <math.h>

#define Tn   128
#define Bn   64
#define Hn   1024
#define NUn  256
#define Vn   8000
#define FH   4096
#define NBLK 96
#define APLANE 4194304   // 8192*512 bytes: one plane of an A-frag image (M=8192,K=256)

// ------------------------------ device scratch ----------------------------
__device__ float g_GX0[Tn * Bn * FH];     // BN(x@Wx0) with gx0 folded
__device__ float g_H1[Bn * Tn * Hn];      // h1 history, row (b*T+t)
__device__ float g_Y[Bn * Tn * NUn];      // projection output (fp32, exact)

// scan weights: A-fragment images, fp16 (hi plane | lo plane per CTA slice)
__device__ __align__(16) unsigned char g_W0f [32 * 524288];
__device__ __align__(16) unsigned char g_W1xf[64 * 262144];
__device__ __align__(16) unsigned char g_W1hf[64 * 262144];
// h states as B-fragment images, single fp16 plane: [parity][128KB]
__device__ __align__(16) unsigned char g_h0B[2][131072];
__device__ __align__(16) unsigned char g_h1B[2][131072];
// A-frag images of activations (bf16 hi|lo planes of 4MB each)
__device__ __align__(16) unsigned char g_Xf[2 * APLANE];
__device__ __align__(16) unsigned char g_Yf[2 * APLANE];
// B-frag images (bf16) of Wx0 (K=256,N=4096) and softmax_w (K=256,N=8000)
__device__ __align__(16) unsigned char g_Wx0B[2 * 4096 * 512];
__device__ __align__(16) unsigned char g_swB [2 * 8000 * 512];

__device__ unsigned g_barCnt;
__device__ volatile unsigned g_barGen;

__device__ __forceinline__ float sigm(float x) { return __fdividef(1.f, 1.f + __expf(-x)); }

// bf16 MMA (pre/post GEMMs, 3-product)
#define MMAB(c, a, b) \
    asm volatile("mma.sync.aligned.m16n8k16.row.col.f32.bf16.bf16.f32 " \
        "{%0,%1,%2,%3},{%4,%5,%6,%7},{%8,%9},{%0,%1,%2,%3};" \
        : "+f"((c)[0]), "+f"((c)[1]), "+f"((c)[2]), "+f"((c)[3]) \
        : "r"((a).x), "r"((a).y), "r"((a).z), "r"((a).w), "r"((b).x), "r"((b).y))
// fp16 MMA (scan, 2-product)
#define MMAH(c, a, b) \
    asm volatile("mma.sync.aligned.m16n8k16.row.col.f32.f16.f16.f32 " \
        "{%0,%1,%2,%3},{%4,%5,%6,%7},{%8,%9},{%0,%1,%2,%3};" \
        : "+f"((c)[0]), "+f"((c)[1]), "+f"((c)[2]), "+f"((c)[3]) \
        : "r"((a).x), "r"((a).y), "r"((a).z), "r"((a).w), "r"((b).x), "r"((b).y))

__device__ __forceinline__ uint32_t smem_u32(const void* p) {
    uint32_t a;
    asm("{ .reg .u64 t; cvta.to.shared.u64 t, %1; cvt.u32.u64 %0, t; }" : "=r"(a) : "l"(p));
    return a;
}
__device__ __forceinline__ void cpa16(uint32_t dst, const void* src) {
    asm volatile("cp.async.cg.shared.global [%0], [%1], 16;" :: "r"(dst), "l"(src) : "memory");
}
#define CP_COMMIT() asm volatile("cp.async.commit_group;" ::: "memory")
#define CP_WAIT(n)  asm volatile("cp.async.wait_group %0;" :: "n"(n) : "memory")

__device__ __forceinline__ void grid_bar() {
    __syncthreads();
    if (threadIdx.x == 0) {
        unsigned gen = g_barGen;
        __threadfence();
        if (atomicAdd(&g_barCnt, 1u) == NBLK - 1) {
            g_barCnt = 0;
            __threadfence();
            g_barGen = gen + 1;
        } else {
            while (g_barGen == gen) { __nanosleep(64); }
        }
        __threadfence();
    }
    __syncthreads();
}

// A-fragment offset for element (row m, col k) in a K=256 image
__device__ __forceinline__ size_t afrag_off(int m, int k) {
    int mt = m >> 4, mi = m & 15, kt = k >> 4, ki = k & 15;
    int lane = (mi & 7) * 4 + ((ki & 7) >> 1);
    int reg  = (mi >> 3) + ((ki >> 3) << 1);
    return ((size_t)(mt * 16 + kt) << 9) + lane * 16 + (reg << 2) + ((ki & 1) << 1);
}
// B-fragment offset for element (k, col n) in a K=256 image (ntile-major)
__device__ __forceinline__ size_t bfrag_off(int k, int n) {
    int nt = n >> 3, ni = n & 7, kt = k >> 4, ki = k & 15;
    int ln = ni * 4 + ((ki & 7) >> 1);
    return ((size_t)(nt * 16 + kt) << 8) + ln * 8 + ((ki >> 3) << 2) + ((ki & 1) << 1);
}

// write one h value into the scan B-frag plane (kt-major tiles, K=1024), fp16
__device__ __forceinline__ void write_hfrag(unsigned char* hb, int b, int hc, float h) {
    int kt = hc >> 4, nt = b >> 3, ki = hc & 15, ni = b & 7;
    int ln = ni * 4 + ((ki & 7) >> 1);
    int off = ((kt * 8 + nt) << 8) + ln * 8 + ((ki >> 3) << 2) + ((ki & 1) << 1);
    *(__half*)(hb + off) = __float2half(h);
}

// ------------------------------ embedding + state init --------------------
__global__ void k_embed(const int* __restrict__ inp, const float* __restrict__ emb) {
    int row = blockIdx.x;                 // t*64 + b
    int u = threadIdx.x;
    int i = blockIdx.x * 256 + threadIdx.x;
    if (i < 65536) ((uint32_t*)g_h0B)[i] = 0u;
    else if (i < 131072) ((uint32_t*)g_h1B)[i - 65536] = 0u;
    int t = row >> 6, b = row & 63;
    float v = emb[(size_t)inp[b * Tn + t] * NUn + u];
    __nv_bfloat16 hi = __float2bfloat16(v);
    __nv_bfloat16 lo = __float2bfloat16(v - __bfloat162float(hi));
    size_t off = afrag_off(row, u);
    *(__nv_bfloat16*)(g_Xf + off) = hi;
    *(__nv_bfloat16*)(g_Xf + APLANE + off) = lo;
}

// ------------------------------ Y fp32 -> A-frags (bf16) ------------------
__global__ void k_fragA(const float* __restrict__ Y) {
    int row = blockIdx.x, u = threadIdx.x;
    float v = Y[(size_t)row * NUn + u];
    __nv_bfloat16 hi = __float2bfloat16(v);
    __nv_bfloat16 lo = __float2bfloat16(v - __bfloat162float(hi));
    size_t off = afrag_off(row, u);
    *(__nv_bfloat16*)(g_Yf + off) = hi;
    *(__nv_bfloat16*)(g_Yf + APLANE + off) = lo;
}

// ------------------------------ weights -> B-frags (merged, bf16) ---------
__global__ void k_prepB(const float* __restrict__ Wx0, const float* __restrict__ sw) {
    int idx = blockIdx.x * 256 + threadIdx.x;
    const float* W; unsigned char* dst; int N; int local;
    if (idx < NUn * FH) { W = Wx0; dst = g_Wx0B; N = FH; local = idx; }
    else { W = sw; dst = g_swB; N = Vn; local = idx - NUn * FH; }
    int k = local / N, n = local - k * N;
    float v = W[local];
    __nv_bfloat16 hi = __float2bfloat16(v);
    __nv_bfloat16 lo = __float2bfloat16(v - __bfloat162float(hi));
    size_t off = bfrag_off(k, n);
    *(__nv_bfloat16*)(dst + off) = hi;
    *(__nv_bfloat16*)(dst + (size_t)N * 512 + off) = lo;
}

// ------------------------------ scan weight prep (fp16 hi/lo) -------------
__global__ void k_prepw(const float* __restrict__ Wh0, const float* __restrict__ Wx1,
                        const float* __restrict__ Wh1) {
    int which = blockIdx.y;
    const float* W = which == 0 ? Wh0 : (which == 1 ? Wx1 : Wh1);
    int idx = blockIdx.x * 256 + threadIdx.x;   // k*4096 + gcol
    int k = idx >> 12, gcol = idx & 4095;
    float wv = W[idx];
    __half hi = __float2half(wv);
    __half lo = __float2half(wv - __half2float(hi));
    int g = gcol >> 10, hc = gcol & 1023;
    unsigned char* base;
    int MT, losz, m;
    if (which == 0) {
        int c = hc >> 5; m = g * 32 + (hc & 31); MT = 8; losz = 262144;
        base = g_W0f + (size_t)c * 524288;
    } else {
        int c = hc >> 4; m = g * 16 + (hc & 15); MT = 4; losz = 131072;
        base = (which == 1 ? g_W1xf : g_W1hf) + (size_t)c * 262144;
    }
    int kt = k >> 4, ki = k & 15, mt = m >> 4, mi = m & 15;
    int lane = (mi & 7) * 4 + ((ki & 7) >> 1);
    int reg  = (mi >> 3) + ((ki >> 3) << 1);
    int off  = ((kt * MT + mt) << 9) + lane * 16 + (reg << 2) + ((ki & 1) << 1);
    *(__half*)(base + off) = hi;
    *(__half*)(base + losz + off) = lo;
}

// ------------------------------ MMA GEMM, K=256 (bf16 3-product) ----------
__global__ void __launch_bounds__(256) k_gemm_mma(
        const unsigned char* __restrict__ Af, const unsigned char* __restrict__ Bf,
        const float* __restrict__ bias, float* __restrict__ C, int N) {
    extern __shared__ unsigned char sb[];
    const int tid = threadIdx.x, w = tid >> 5, lane = tid & 31;
    const int nb = blockIdx.x, mb = blockIdx.y;
    {
        int p = tid >> 7, o = (tid & 127) * 16;
        const unsigned char* src = Bf + (size_t)p * ((size_t)N * 512) + (size_t)nb * 32768 + o;
        uint32_t dst = smem_u32(sb + p * 32768 + o);
#pragma unroll
        for (int i = 0; i < 16; i++) cpa16(dst + i * 2048, src + i * 2048);
        CP_COMMIT(); CP_WAIT(0);
    }
    __syncthreads();
    const size_t abase = ((size_t)(mb * 8 + w) << 13) + lane * 16;
    uint4 ahc = *(const uint4*)(Af + abase);
    uint4 alc = *(const uint4*)(Af + APLANE + abase);
    float acc[8][4] = {};
#pragma unroll
    for (int kt = 0; kt < 16; kt++) {
        uint4 ahn, aln;
        if (kt < 15) {
            ahn = *(const uint4*)(Af + abase + (kt + 1) * 512);
            aln = *(const uint4*)(Af + APLANE + abase + (kt + 1) * 512);
        }
        uint2 bh[8], bl[8];
#pragma unroll
        for (int j = 0; j < 8; j++) {
            bh[j] = *(const uint2*)(sb + (j * 16 + kt) * 256 + lane * 8);
            bl[j] = *(const uint2*)(sb + 32768 + (j * 16 + kt) * 256 + lane * 8);
        }
#pragma unroll
        for (int j = 0; j < 8; j++) MMAB(acc[j], ahc, bh[j]);
#pragma unroll
        for (int j = 0; j < 8; j++) MMAB(acc[j], alc, bh[j]);
#pragma unroll
        for (int j = 0; j < 8; j++) MMAB(acc[j], ahc, bl[j]);
        ahc = ahn; alc = aln;
    }
    int r0 = mb * 128 + w * 16 + (lane >> 2);
#pragma unroll
    for (int j = 0; j < 8; j++) {
        int col = nb * 64 + j * 8 + (lane & 3) * 2;
        float b0v = bias ? bias[col] : 0.f;
        float b1v = bias ? bias[col + 1] : 0.f;
        *(float2*)(C + (size_t)r0 * N + col) = make_float2(acc[j][0] + b0v, acc[j][1] + b1v);
        *(float2*)(C + (size_t)(r0 + 8) * N + col) = make_float2(acc[j][2] + b0v, acc[j][3] + b1v);
    }
}

// ------------------------------ fp32 GEMM (Wp only) -----------------------
__global__ void k_gemm(const float* __restrict__ A, const float* __restrict__ B,
                       const float* __restrict__ bias, float* __restrict__ C,
                       int M, int N, int K) {
    __shared__ float As[32][129];
    __shared__ float Bs[32][64];
    int tid = threadIdx.x;
    int bm = blockIdx.y * 128, bn = blockIdx.x * 64;
    int tx = tid & 15, ty = tid >> 4;
    float acc[8][4] = {};
    for (int k0 = 0; k0 < K; k0 += 32) {
#pragma unroll
        for (int i = 0; i < 16; i++) {
            int idx = tid + i * 256;
            int m = idx >> 5, k = idx & 31;
            As[k][m] = A[(long)(bm + m) * K + k0 + k];
        }
#pragma unroll
        for (int i = 0; i < 8; i++) {
            int idx = tid + i * 256;
            int k = idx >> 6, n = idx & 63;
            Bs[k][n] = B[(long)(k0 + k) * N + bn + n];
        }
        __syncthreads();
#pragma unroll
        for (int k = 0; k < 32; k++) {
            float b4[4];
#pragma unroll
            for (int j = 0; j < 4; j++) b4[j] = Bs[k][tx * 4 + j];
#pragma unroll
            for (int i = 0; i < 8; i++) {
                float a = As[k][ty * 8 + i];
#pragma unroll
                for (int j = 0; j < 4; j++) acc[i][j] += a * b4[j];
            }
        }
        __syncthreads();
    }
#pragma unroll
    for (int i = 0; i < 8; i++) {
        int m = bm + ty * 8 + i;
#pragma unroll
        for (int j = 0; j < 4; j++) {
            int n = bn + tx * 4 + j;
            C[(long)m * N + n] = acc[i][j] + (bias ? bias[n] : 0.f);
        }
    }
}

// ------------------------------ BN of X@Wx0 -------------------------------
__global__ void k_bnx(const float* __restrict__ gx0) {
    int idx = blockIdx.x * 256 + threadIdx.x;
    int t = idx >> 12, c = idx & 4095;
    int base = (t * 64) * FH + c;
    float s = 0.f, s2 = 0.f;
#pragma unroll
    for (int b = 0; b < 64; b++) {
        float v = g_GX0[base + b * FH];
        s += v; s2 += v * v;
    }
    float m = s * (1.f / 64.f);
    float var = fmaxf(s2 * (1.f / 64.f) - m * m, 0.f);
    float scl = gx0[c] * rsqrtf(var + 1e-5f);
#pragma unroll
    for (int b = 0; b < 64; b++)
        g_GX0[base + b * FH] = scl * (g_GX0[base + b * FH] - m);
}

// ------------------------------ persistent scan (fp16, 2-product) ---------
// 96 CTAs x 512 thr. CTAs 0..31: layer0 (32 hcols). CTAs 32..95: layer1 (16).
// W fp16 hi/lo (2 products), h single fp16 plane. B double-buffered 2x32KB.
__global__ void __launch_bounds__(512) k_scan(
        const float* __restrict__ b0,  const float* __restrict__ gh0,
        const float* __restrict__ gc0, const float* __restrict__ bc0,
        const float* __restrict__ b1,  const float* __restrict__ gx1,
        const float* __restrict__ gh1, const float* __restrict__ gc1,
        const float* __restrict__ bc1) {
    extern __shared__ __align__(16) unsigned char sm[];
    float (*Cs)[65] = (float(*)[65])sm;            // epilogue aliases buffers
    float* psA  = (float*)(sm + 65536);            // 512
    float* ps2A = psA + 512;                       // 512
    float* mcA  = ps2A + 512;                      // 32
    float* rsA  = mcA + 32;                        // 32

    const int tid = threadIdx.x, wid = tid >> 5, lane = tid & 31;
    const bool isL1 = blockIdx.x >= 32;
    const int c = isL1 ? (int)blockIdx.x - 32 : (int)blockIdx.x;

    float creg[4] = {0.f, 0.f, 0.f, 0.f};

    for (int t = 0; t <= Tn; t++) {
        if (!isL1 && t < Tn) {
            const int u = t;
            const unsigned char* Ah = g_W0f + (size_t)c * 524288;
            const unsigned char* Bg = g_h0B[u & 1];
            const int mt = wid & 7, nh = wid >> 3;
            const int cpo = tid * 64;              // 512 thr x 64B = 32KB chunk
#pragma unroll
            for (int k0 = 0; k0 < 2; k0++) {
                const unsigned char* src = Bg + k0 * 32768 + cpo;
                uint32_t dst = smem_u32(sm + k0 * 32768 + cpo);
#pragma unroll
                for (int i = 0; i < 4; i++) cpa16(dst + i * 16, src + i * 16);
                CP_COMMIT();
            }
            uint4 ahc = *(const uint4*)(Ah + ((size_t)mt << 9) + lane * 16);
            uint4 alc = *(const uint4*)(Ah + 262144 + ((size_t)mt << 9) + lane * 16);
            float acc[4][4] = {};
            for (int kt = 0; kt < 64; kt++) {
                int kc = kt >> 4;
                if ((kt & 15) == 0) {
                    if (kc < 3) { CP_WAIT(1); } else { CP_WAIT(0); }
                    __syncthreads();
                }
                uint4 ahn, aln;
                if (kt < 63) {
                    size_t ao = ((size_t)((kt + 1) * 8 + mt) << 9) + lane * 16;
                    ahn = *(const uint4*)(Ah + ao);
                    aln = *(const uint4*)(Ah + 262144 + ao);
                }
                const unsigned char* bb = sm + (kc & 1) * 32768 + ((kt & 15) << 11) + (nh << 10);
                uint2 bh[4];
#pragma unroll
                for (int j = 0; j < 4; j++)
                    bh[j] = *(const uint2*)(bb + (j << 8) + lane * 8);
#pragma unroll
                for (int j = 0; j < 4; j++) MMAH(acc[j], ahc, bh[j]);
#pragma unroll
                for (int j = 0; j < 4; j++) MMAH(acc[j], alc, bh[j]);
                if ((kt & 15) == 15) {
                    __syncthreads();
                    if (kc + 2 < 4) {
                        const unsigned char* src = Bg + (kc + 2) * 32768 + cpo;
                        uint32_t dst = smem_u32(sm + (kc & 1) * 32768 + cpo);
#pragma unroll
                        for (int i = 0; i < 4; i++) cpa16(dst + i * 16, src + i * 16);
                        CP_COMMIT();
                    }
                }
                ahc = ahn; alc = aln;
            }
            __syncthreads();
            // ---------------- epilogue L0 ----------------
#pragma unroll
            for (int j = 0; j < 4; j++) {
                int r0 = mt * 16 + (lane >> 2);
                int cl = (nh * 4 + j) * 8 + (lane & 3) * 2;
                Cs[r0][cl] = acc[j][0]; Cs[r0][cl + 1] = acc[j][1];
                Cs[r0 + 8][cl] = acc[j][2]; Cs[r0 + 8][cl + 1] = acc[j][3];
            }
            __syncthreads();
            {   // BN row pass: 4 threads per row
                int r = tid >> 2, q = tid & 3;
                float s = 0.f, s2 = 0.f;
#pragma unroll
                for (int i = 0; i < 16; i++) {
                    float v = Cs[r][q * 16 + i]; s += v; s2 += v * v;
                }
                s  += __shfl_xor_sync(0xffffffffu, s, 1);
                s  += __shfl_xor_sync(0xffffffffu, s, 2);
                s2 += __shfl_xor_sync(0xffffffffu, s2, 1);
                s2 += __shfl_xor_sync(0xffffffffu, s2, 2);
                float m = s * (1.f / 64.f);
                float var = fmaxf(s2 * (1.f / 64.f) - m * m, 0.f);
                float gam = gh0[(r >> 5) * Hn + c * 32 + (r & 31)];
                float sc = gam * rsqrtf(var + 1e-5f);
#pragma unroll
                for (int i = 0; i < 16; i++)
                    Cs[r][q * 16 + i] = sc * (Cs[r][q * 16 + i] - m);
            }
            __syncthreads();
            int hcl = tid & 31, bg = tid >> 5;     // 16 b-groups of 4
            int hc = c * 32 + hcl;
            float ov[4], ps = 0.f, p2 = 0.f;
            float bI = b0[hc], bJ = b0[Hn + hc], bF = b0[2 * Hn + hc], bO = b0[3 * Hn + hc];
#pragma unroll
            for (int i = 0; i < 4; i++) {
                int b = bg * 4 + i;
                const float* gx = g_GX0 + (size_t)(u * 64 + b) * FH;
                float preI = Cs[hcl][b]      + gx[hc]          + bI;
                float preJ = Cs[32 + hcl][b] + gx[Hn + hc]     + bJ;
                float preF = Cs[64 + hcl][b] + gx[2 * Hn + hc] + bF;
                float preO = Cs[96 + hcl][b] + gx[3 * Hn + hc] + bO;
                float cn = sigm(preF + 1.f) * creg[i] + sigm(preI) * tanhf(preJ);
                creg[i] = cn; ov[i] = preO; ps += cn; p2 += cn * cn;
            }
            psA[bg * 32 + hcl] = ps; ps2A[bg * 32 + hcl] = p2;
            __syncthreads();
            if (tid < 32) {
                float s = 0.f, s2 = 0.f;
#pragma unroll
                for (int g = 0; g < 16; g++) { s += psA[g * 32 + tid]; s2 += ps2A[g * 32 + tid]; }
                float m = s * (1.f / 64.f);
                float var = fmaxf(s2 * (1.f / 64.f) - m * m, 0.f);
                mcA[tid] = m; rsA[tid] = rsqrtf(var + 1e-5f);
            }
            __syncthreads();
            float gcv = gc0[hc], bcv = bc0[hc], mm = mcA[hcl], rr = rsA[hcl];
            unsigned char* hb = g_h0B[(u + 1) & 1];
#pragma unroll
            for (int i = 0; i < 4; i++) {
                float cn = gcv * (creg[i] - mm) * rr + bcv;
                float h = sigm(ov[i]) * tanhf(cn);
                write_hfrag(hb, bg * 4 + i, hc, h);
            }
        } else if (isL1 && t >= 1) {
            const int u = t - 1;
            const int g = wid >> 3, mt = (wid >> 1) & 3, nh = wid & 1;
            const unsigned char* Ag = (g == 0 ? g_W1xf : g_W1hf) + (size_t)c * 262144;
            const unsigned char* BB[2] = { g_h0B[(u + 1) & 1], g_h1B[u & 1] };
            const int gsel = g * 16384;
            const int sg = tid >> 8, cpo = (tid & 255) * 64;  // 256 thr x 64B = 16KB per gemm
#pragma unroll
            for (int k0 = 0; k0 < 2; k0++) {
                const unsigned char* src = BB[sg] + k0 * 16384 + cpo;
                uint32_t dst = smem_u32(sm + k0 * 32768 + sg * 16384 + cpo);
#pragma unroll
                for (int i = 0; i < 4; i++) cpa16(dst + i * 16, src + i * 16);
                CP_COMMIT();
            }
            uint4 ahc = *(const uint4*)(Ag + ((size_t)mt << 9) + lane * 16);
            uint4 alc = *(const uint4*)(Ag + 131072 + ((size_t)mt << 9) + lane * 16);
            float acc[4][4] = {};
            for (int kt = 0; kt < 64; kt++) {
                int kc = kt >> 3;
                if ((kt & 7) == 0) {
                    if (kc < 7) { CP_WAIT(1); } else { CP_WAIT(0); }
                    __syncthreads();
                }
                uint4 ahn, aln;
                if (kt < 63) {
                    size_t ao = ((size_t)((kt + 1) * 4 + mt) << 9) + lane * 16;
                    ahn = *(const uint4*)(Ag + ao);
                    aln = *(const uint4*)(Ag + 131072 + ao);
                }
                const unsigned char* bb = sm + (kc & 1) * 32768 + gsel + ((kt & 7) << 11) + (nh << 10);
                uint2 bh[4];
#pragma unroll
                for (int j = 0; j < 4; j++)
                    bh[j] = *(const uint2*)(bb + (j << 8) + lane * 8);
#pragma unroll
                for (int j = 0; j < 4; j++) MMAH(acc[j], ahc, bh[j]);
#pragma unroll
                for (int j = 0; j < 4; j++) MMAH(acc[j], alc, bh[j]);
                if ((kt & 7) == 7) {
                    __syncthreads();
                    if (kc + 2 < 8) {
                        const unsigned char* src = BB[sg] + (kc + 2) * 16384 + cpo;
                        uint32_t dst = smem_u32(sm + (kc & 1) * 32768 + sg * 16384 + cpo);
#pragma unroll
                        for (int i = 0; i < 4; i++) cpa16(dst + i * 16, src + i * 16);
                        CP_COMMIT();
                    }
                }
                ahc = ahn; alc = aln;
            }
            __syncthreads();
            // ---------------- epilogue L1 ----------------
#pragma unroll
            for (int j = 0; j < 4; j++) {
                int r0 = g * 64 + mt * 16 + (lane >> 2);
                int cl = (nh * 4 + j) * 8 + (lane & 3) * 2;
                Cs[r0][cl] = acc[j][0]; Cs[r0][cl + 1] = acc[j][1];
                Cs[r0 + 8][cl] = acc[j][2]; Cs[r0 + 8][cl + 1] = acc[j][3];
            }
            __syncthreads();
            {   // BN row pass: 4 threads per row
                int r = tid >> 2, q = tid & 3, rr = r & 63;
                float s = 0.f, s2 = 0.f;
#pragma unroll
                for (int i = 0; i < 16; i++) {
                    float v = Cs[r][q * 16 + i]; s += v; s2 += v * v;
                }
                s  += __shfl_xor_sync(0xffffffffu, s, 1);
                s  += __shfl_xor_sync(0xffffffffu, s, 2);
                s2 += __shfl_xor_sync(0xffffffffu, s2, 1);
                s2 += __shfl_xor_sync(0xffffffffu, s2, 2);
                float m = s * (1.f / 64.f);
                float var = fmaxf(s2 * (1.f / 64.f) - m * m, 0.f);
                int gi = (rr >> 4) * Hn + c * 16 + (rr & 15);
                float gam = (r < 64) ? gx1[gi] : gh1[gi];
                float sc = gam * rsqrtf(var + 1e-5f);
#pragma unroll
                for (int i = 0; i < 16; i++)
                    Cs[r][q * 16 + i] = sc * (Cs[r][q * 16 + i] - m);
            }
            __syncthreads();
            int hcl = tid & 15, bg = tid >> 4;     // 32 b-groups of 2
            int hc = c * 16 + hcl;
            float ov[2], ps = 0.f, p2 = 0.f;
            float bI = b1[hc], bJ = b1[Hn + hc], bF = b1[2 * Hn + hc], bO = b1[3 * Hn + hc];
#pragma unroll
            for (int i = 0; i < 2; i++) {
                int b = bg * 2 + i;
                float preI = Cs[hcl][b]      + Cs[64 + hcl][b]  + bI;
                float preJ = Cs[16 + hcl][b] + Cs[80 + hcl][b]  + bJ;
                float preF = Cs[32 + hcl][b] + Cs[96 + hcl][b]  + bF;
                float preO = Cs[48 + hcl][b] + Cs[112 + hcl][b] + bO;
                float cn = sigm(preF + 1.f) * creg[i] + sigm(preI) * tanhf(preJ);
                creg[i] = cn; ov[i] = preO; ps += cn; p2 += cn * cn;
            }
            psA[bg * 16 + hcl] = ps; ps2A[bg * 16 + hcl] = p2;
            __syncthreads();
            if (tid < 16) {
                float s = 0.f, s2 = 0.f;
#pragma unroll
                for (int gg = 0; gg < 32; gg++) { s += psA[gg * 16 + tid]; s2 += ps2A[gg * 16 + tid]; }
                float m = s * (1.f / 64.f);
                float var = fmaxf(s2 * (1.f / 64.f) - m * m, 0.f);
                mcA[tid] = m; rsA[tid] = rsqrtf(var + 1e-5f);
            }
            __syncthreads();
            float gcv = gc1[hc], bcv = bc1[hc], mm = mcA[hcl], rr = rsA[hcl];
            unsigned char* hb = g_h1B[(u + 1) & 1];
#pragma unroll
            for (int i = 0; i < 2; i++) {
                int b = bg * 2 + i;
                float cn = gcv * (creg[i] - mm) * rr + bcv;
                float h = sigm(ov[i]) * tanhf(cn);
                write_hfrag(hb, b, hc, h);
                g_H1[((size_t)b * Tn + u) * Hn + hc] = h;
            }
        }
        grid_bar();
    }
}

// ------------------------------ launch ------------------------------------
extern "C" void kernel_launch(void* const* d_in, const int* in_sizes, int n_in,
                              void* d_out, int out_size) {
    const int*   inp = (const int*)  d_in[0];
    const float* emb = (const float*)d_in[1];
    const float* Wx0 = (const float*)d_in[2];
    const float* Wh0 = (const float*)d_in[3];
    const float* b0  = (const float*)d_in[4];
    const float* gx0 = (const float*)d_in[5];
    const float* gh0 = (const float*)d_in[6];
    const float* gc0 = (const float*)d_in[7];
    const float* bc0 = (const float*)d_in[8];
    const float* Wx1 = (const float*)d_in[9];
    const float* Wh1 = (const float*)d_in[10];
    const float* b1  = (const float*)d_in[11];
    const float* gx1 = (const float*)d_in[12];
    const float* gh1 = (const float*)d_in[13];
    const float* gc1 = (const float*)d_in[14];
    const float* bc1 = (const float*)d_in[15];
    const float* Wp  = (const float*)d_in[16];
    const float* bp  = (const float*)d_in[17];
    const float* sw  = (const float*)d_in[18];
    const float* sb  = (const float*)d_in[19];
    float* out = (float*)d_out;

    float *pGX0, *pH1, *pY;
    unsigned char *pXf, *pYf, *pWx0B, *pswB;
    cudaGetSymbolAddress((void**)&pGX0, g_GX0);
    cudaGetSymbolAddress((void**)&pH1,  g_H1);
    cudaGetSymbolAddress((void**)&pY,   g_Y);
    cudaGetSymbolAddress((void**)&pXf,  g_Xf);
    cudaGetSymbolAddress((void**)&pYf,  g_Yf);
    cudaGetSymbolAddress((void**)&pWx0B, g_Wx0B);
    cudaGetSymbolAddress((void**)&pswB,  g_swB);

    cudaFuncSetAttribute(k_scan, cudaFuncAttributeMaxDynamicSharedMemorySize, 69888);
    cudaFuncSetAttribute(k_gemm_mma, cudaFuncAttributeMaxDynamicSharedMemorySize, 65536);

    // launch order arranged so k_scan is the 6th launch (ncu -s 5 -c 1)
    k_embed<<<Tn * Bn, 256>>>(inp, emb);                        // 1 (init fused)
    k_prepw<<<dim3(16384, 3), 256>>>(Wh0, Wx1, Wh1);            // 2
    k_prepB<<<(NUn * (FH + Vn)) / 256, 256>>>(Wx0, sw);         // 3
    k_gemm_mma<<<dim3(FH / 64, 64), 256, 65536>>>(pXf, pWx0B, nullptr, pGX0, FH);  // 4
    k_bnx<<<(Tn * FH) / 256, 256>>>(gx0);                       // 5
    k_scan<<<NBLK, 512, 69888>>>(b0, gh0, gc0, bc0, b1, gx1, gh1, gc1, bc1);       // 6
    k_gemm<<<dim3(NUn / 64, (Tn * Bn) / 128), 256>>>(pH1, Wp, bp, pY,
                                                     Tn * Bn, NUn, Hn);
    k_fragA<<<Tn * Bn, 256>>>(pY);
    k_gemm_mma<<<dim3(Vn / 64, 64), 256, 65536>>>(pYf, pswB, sb, out, Vn);
}

// round 10
// speedup vs baseline: 5.0724x; 1.1538x over previous
#include <cuda_runtime.h>
#include <cuda_bf16.h>
#include <cuda_fp16.h>
#include <cstdint>
#include <math.h>

#define Tn   128
#define Bn   64
#define Hn   1024
#define NUn  256
#define Vn   8000
#define FH   4096
#define NBLK 96
#define APLANE 4194304   // 8192*512 bytes: one plane of an A-frag image (M=8192,K=256)

// ------------------------------ device scratch ----------------------------
__device__ float g_GX0[Tn * Bn * FH];     // BN(x@Wx0) with gx0 folded
__device__ float g_H1[Bn * Tn * Hn];      // h1 history, row (b*T+t)
__device__ float g_Y[Bn * Tn * NUn];      // projection output (fp32, exact)

// scan weights: A-fragment images, SINGLE fp16 plane per CTA slice
__device__ __align__(16) unsigned char g_W0f [32 * 262144];
__device__ __align__(16) unsigned char g_W1xf[64 * 131072];
__device__ __align__(16) unsigned char g_W1hf[64 * 131072];
// h states as B-fragment images, single fp16 plane: [parity][128KB]
__device__ __align__(16) unsigned char g_h0B[2][131072];
__device__ __align__(16) unsigned char g_h1B[2][131072];
// A-frag images of activations (bf16 hi|lo planes of 4MB each)
__device__ __align__(16) unsigned char g_Xf[2 * APLANE];
__device__ __align__(16) unsigned char g_Yf[2 * APLANE];
// B-frag images (bf16) of Wx0 (K=256,N=4096) and softmax_w (K=256,N=8000)
__device__ __align__(16) unsigned char g_Wx0B[2 * 4096 * 512];
__device__ __align__(16) unsigned char g_swB [2 * 8000 * 512];

__device__ unsigned g_barCnt;
__device__ volatile unsigned g_barGen;

__device__ __forceinline__ float sigm(float x) { return __fdividef(1.f, 1.f + __expf(-x)); }

// bf16 MMA (pre/post GEMMs, 3-product)
#define MMAB(c, a, b) \
    asm volatile("mma.sync.aligned.m16n8k16.row.col.f32.bf16.bf16.f32 " \
        "{%0,%1,%2,%3},{%4,%5,%6,%7},{%8,%9},{%0,%1,%2,%3};" \
        : "+f"((c)[0]), "+f"((c)[1]), "+f"((c)[2]), "+f"((c)[3]) \
        : "r"((a).x), "r"((a).y), "r"((a).z), "r"((a).w), "r"((b).x), "r"((b).y))
// fp16 MMA (scan, single product)
#define MMAH(c, a, b) \
    asm volatile("mma.sync.aligned.m16n8k16.row.col.f32.f16.f16.f32 " \
        "{%0,%1,%2,%3},{%4,%5,%6,%7},{%8,%9},{%0,%1,%2,%3};" \
        : "+f"((c)[0]), "+f"((c)[1]), "+f"((c)[2]), "+f"((c)[3]) \
        : "r"((a).x), "r"((a).y), "r"((a).z), "r"((a).w), "r"((b).x), "r"((b).y))

__device__ __forceinline__ uint32_t smem_u32(const void* p) {
    uint32_t a;
    asm("{ .reg .u64 t; cvta.to.shared.u64 t, %1; cvt.u32.u64 %0, t; }" : "=r"(a) : "l"(p));
    return a;
}
__device__ __forceinline__ void cpa16(uint32_t dst, const void* src) {
    asm volatile("cp.async.cg.shared.global [%0], [%1], 16;" :: "r"(dst), "l"(src) : "memory");
}
#define CP_COMMIT() asm volatile("cp.async.commit_group;" ::: "memory")
#define CP_WAIT(n)  asm volatile("cp.async.wait_group %0;" :: "n"(n) : "memory")

__device__ __forceinline__ void grid_bar() {
    __syncthreads();
    if (threadIdx.x == 0) {
        unsigned gen = g_barGen;
        __threadfence();
        if (atomicAdd(&g_barCnt, 1u) == NBLK - 1) {
            g_barCnt = 0;
            __threadfence();
            g_barGen = gen + 1;
        } else {
            while (g_barGen == gen) { __nanosleep(64); }
        }
        __threadfence();
    }
    __syncthreads();
}

// A-fragment offset for element (row m, col k) in a K=256 image
__device__ __forceinline__ size_t afrag_off(int m, int k) {
    int mt = m >> 4, mi = m & 15, kt = k >> 4, ki = k & 15;
    int lane = (mi & 7) * 4 + ((ki & 7) >> 1);
    int reg  = (mi >> 3) + ((ki >> 3) << 1);
    return ((size_t)(mt * 16 + kt) << 9) + lane * 16 + (reg << 2) + ((ki & 1) << 1);
}
// B-fragment offset for element (k, col n) in a K=256 image (ntile-major)
__device__ __forceinline__ size_t bfrag_off(int k, int n) {
    int nt = n >> 3, ni = n & 7, kt = k >> 4, ki = k & 15;
    int ln = ni * 4 + ((ki & 7) >> 1);
    return ((size_t)(nt * 16 + kt) << 8) + ln * 8 + ((ki >> 3) << 2) + ((ki & 1) << 1);
}

// write one h value into the scan B-frag plane (kt-major tiles, K=1024), fp16
__device__ __forceinline__ void write_hfrag(unsigned char* hb, int b, int hc, float h) {
    int kt = hc >> 4, nt = b >> 3, ki = hc & 15, ni = b & 7;
    int ln = ni * 4 + ((ki & 7) >> 1);
    int off = ((kt * 8 + nt) << 8) + ln * 8 + ((ki >> 3) << 2) + ((ki & 1) << 1);
    *(__half*)(hb + off) = __float2half(h);
}

// ------------------------------ embedding + state init --------------------
__global__ void k_embed(const int* __restrict__ inp, const float* __restrict__ emb) {
    int row = blockIdx.x;                 // t*64 + b
    int u = threadIdx.x;
    int i = blockIdx.x * 256 + threadIdx.x;
    if (i < 65536) ((uint32_t*)g_h0B)[i] = 0u;
    else if (i < 131072) ((uint32_t*)g_h1B)[i - 65536] = 0u;
    int t = row >> 6, b = row & 63;
    float v = emb[(size_t)inp[b * Tn + t] * NUn + u];
    __nv_bfloat16 hi = __float2bfloat16(v);
    __nv_bfloat16 lo = __float2bfloat16(v - __bfloat162float(hi));
    size_t off = afrag_off(row, u);
    *(__nv_bfloat16*)(g_Xf + off) = hi;
    *(__nv_bfloat16*)(g_Xf + APLANE + off) = lo;
}

// ------------------------------ Y fp32 -> A-frags (bf16) ------------------
__global__ void k_fragA(const float* __restrict__ Y) {
    int row = blockIdx.x, u = threadIdx.x;
    float v = Y[(size_t)row * NUn + u];
    __nv_bfloat16 hi = __float2bfloat16(v);
    __nv_bfloat16 lo = __float2bfloat16(v - __bfloat162float(hi));
    size_t off = afrag_off(row, u);
    *(__nv_bfloat16*)(g_Yf + off) = hi;
    *(__nv_bfloat16*)(g_Yf + APLANE + off) = lo;
}

// ------------------------------ weights -> B-frags (merged, bf16) ---------
__global__ void k_prepB(const float* __restrict__ Wx0, const float* __restrict__ sw) {
    int idx = blockIdx.x * 256 + threadIdx.x;
    const float* W; unsigned char* dst; int N; int local;
    if (idx < NUn * FH) { W = Wx0; dst = g_Wx0B; N = FH; local = idx; }
    else { W = sw; dst = g_swB; N = Vn; local = idx - NUn * FH; }
    int k = local / N, n = local - k * N;
    float v = W[local];
    __nv_bfloat16 hi = __float2bfloat16(v);
    __nv_bfloat16 lo = __float2bfloat16(v - __bfloat162float(hi));
    size_t off = bfrag_off(k, n);
    *(__nv_bfloat16*)(dst + off) = hi;
    *(__nv_bfloat16*)(dst + (size_t)N * 512 + off) = lo;
}

// ------------------------------ scan weight prep (single fp16) ------------
__global__ void k_prepw(const float* __restrict__ Wh0, const float* __restrict__ Wx1,
                        const float* __restrict__ Wh1) {
    int which = blockIdx.y;
    const float* W = which == 0 ? Wh0 : (which == 1 ? Wx1 : Wh1);
    int idx = blockIdx.x * 256 + threadIdx.x;   // k*4096 + gcol
    int k = idx >> 12, gcol = idx & 4095;
    __half hv = __float2half(W[idx]);
    int g = gcol >> 10, hc = gcol & 1023;
    unsigned char* base;
    int MT, m;
    if (which == 0) {
        int c = hc >> 5; m = g * 32 + (hc & 31); MT = 8;
        base = g_W0f + (size_t)c * 262144;
    } else {
        int c = hc >> 4; m = g * 16 + (hc & 15); MT = 4;
        base = (which == 1 ? g_W1xf : g_W1hf) + (size_t)c * 131072;
    }
    int kt = k >> 4, ki = k & 15, mt = m >> 4, mi = m & 15;
    int lane = (mi & 7) * 4 + ((ki & 7) >> 1);
    int reg  = (mi >> 3) + ((ki >> 3) << 1);
    int off  = ((kt * MT + mt) << 9) + lane * 16 + (reg << 2) + ((ki & 1) << 1);
    *(__half*)(base + off) = hv;
}

// ------------------------------ MMA GEMM, K=256 (bf16 3-product) ----------
__global__ void __launch_bounds__(256) k_gemm_mma(
        const unsigned char* __restrict__ Af, const unsigned char* __restrict__ Bf,
        const float* __restrict__ bias, float* __restrict__ C, int N) {
    extern __shared__ unsigned char sb[];
    const int tid = threadIdx.x, w = tid >> 5, lane = tid & 31;
    const int nb = blockIdx.x, mb = blockIdx.y;
    {
        int p = tid >> 7, o = (tid & 127) * 16;
        const unsigned char* src = Bf + (size_t)p * ((size_t)N * 512) + (size_t)nb * 32768 + o;
        uint32_t dst = smem_u32(sb + p * 32768 + o);
#pragma unroll
        for (int i = 0; i < 16; i++) cpa16(dst + i * 2048, src + i * 2048);
        CP_COMMIT(); CP_WAIT(0);
    }
    __syncthreads();
    const size_t abase = ((size_t)(mb * 8 + w) << 13) + lane * 16;
    uint4 ahc = *(const uint4*)(Af + abase);
    uint4 alc = *(const uint4*)(Af + APLANE + abase);
    float acc[8][4] = {};
#pragma unroll
    for (int kt = 0; kt < 16; kt++) {
        uint4 ahn, aln;
        if (kt < 15) {
            ahn = *(const uint4*)(Af + abase + (kt + 1) * 512);
            aln = *(const uint4*)(Af + APLANE + abase + (kt + 1) * 512);
        }
        uint2 bh[8], bl[8];
#pragma unroll
        for (int j = 0; j < 8; j++) {
            bh[j] = *(const uint2*)(sb + (j * 16 + kt) * 256 + lane * 8);
            bl[j] = *(const uint2*)(sb + 32768 + (j * 16 + kt) * 256 + lane * 8);
        }
#pragma unroll
        for (int j = 0; j < 8; j++) MMAB(acc[j], ahc, bh[j]);
#pragma unroll
        for (int j = 0; j < 8; j++) MMAB(acc[j], alc, bh[j]);
#pragma unroll
        for (int j = 0; j < 8; j++) MMAB(acc[j], ahc, bl[j]);
        ahc = ahn; alc = aln;
    }
    int r0 = mb * 128 + w * 16 + (lane >> 2);
#pragma unroll
    for (int j = 0; j < 8; j++) {
        int col = nb * 64 + j * 8 + (lane & 3) * 2;
        float b0v = bias ? bias[col] : 0.f;
        float b1v = bias ? bias[col + 1] : 0.f;
        *(float2*)(C + (size_t)r0 * N + col) = make_float2(acc[j][0] + b0v, acc[j][1] + b1v);
        *(float2*)(C + (size_t)(r0 + 8) * N + col) = make_float2(acc[j][2] + b0v, acc[j][3] + b1v);
    }
}

// ------------------------------ fp32 GEMM (Wp only) -----------------------
__global__ void k_gemm(const float* __restrict__ A, const float* __restrict__ B,
                       const float* __restrict__ bias, float* __restrict__ C,
                       int M, int N, int K) {
    __shared__ float As[32][129];
    __shared__ float Bs[32][64];
    int tid = threadIdx.x;
    int bm = blockIdx.y * 128, bn = blockIdx.x * 64;
    int tx = tid & 15, ty = tid >> 4;
    float acc[8][4] = {};
    for (int k0 = 0; k0 < K; k0 += 32) {
#pragma unroll
        for (int i = 0; i < 16; i++) {
            int idx = tid + i * 256;
            int m = idx >> 5, k = idx & 31;
            As[k][m] = A[(long)(bm + m) * K + k0 + k];
        }
#pragma unroll
        for (int i = 0; i < 8; i++) {
            int idx = tid + i * 256;
            int k = idx >> 6, n = idx & 63;
            Bs[k][n] = B[(long)(k0 + k) * N + bn + n];
        }
        __syncthreads();
#pragma unroll
        for (int k = 0; k < 32; k++) {
            float b4[4];
#pragma unroll
            for (int j = 0; j < 4; j++) b4[j] = Bs[k][tx * 4 + j];
#pragma unroll
            for (int i = 0; i < 8; i++) {
                float a = As[k][ty * 8 + i];
#pragma unroll
                for (int j = 0; j < 4; j++) acc[i][j] += a * b4[j];
            }
        }
        __syncthreads();
    }
#pragma unroll
    for (int i = 0; i < 8; i++) {
        int m = bm + ty * 8 + i;
#pragma unroll
        for (int j = 0; j < 4; j++) {
            int n = bn + tx * 4 + j;
            C[(long)m * N + n] = acc[i][j] + (bias ? bias[n] : 0.f);
        }
    }
}

// ------------------------------ BN of X@Wx0 -------------------------------
__global__ void k_bnx(const float* __restrict__ gx0) {
    int idx = blockIdx.x * 256 + threadIdx.x;
    int t = idx >> 12, c = idx & 4095;
    int base = (t * 64) * FH + c;
    float s = 0.f, s2 = 0.f;
#pragma unroll
    for (int b = 0; b < 64; b++) {
        float v = g_GX0[base + b * FH];
        s += v; s2 += v * v;
    }
    float m = s * (1.f / 64.f);
    float var = fmaxf(s2 * (1.f / 64.f) - m * m, 0.f);
    float scl = gx0[c] * rsqrtf(var + 1e-5f);
#pragma unroll
    for (int b = 0; b < 64; b++)
        g_GX0[base + b * FH] = scl * (g_GX0[base + b * FH] - m);
}

// ------------------------------ persistent scan (fp16, 1-product) ---------
// 96 CTAs x 512 thr. CTAs 0..31: layer0 (32 hcols). CTAs 32..95: layer1 (16).
// W single fp16 plane, h single fp16 plane. B double-buffered 2x32KB.
__global__ void __launch_bounds__(512) k_scan(
        const float* __restrict__ b0,  const float* __restrict__ gh0,
        const float* __restrict__ gc0, const float* __restrict__ bc0,
        const float* __restrict__ b1,  const float* __restrict__ gx1,
        const float* __restrict__ gh1, const float* __restrict__ gc1,
        const float* __restrict__ bc1) {
    extern __shared__ __align__(16) unsigned char sm[];
    float (*Cs)[65] = (float(*)[65])sm;            // epilogue aliases buffers
    float* psA  = (float*)(sm + 65536);            // 512
    float* ps2A = psA + 512;                       // 512
    float* mcA  = ps2A + 512;                      // 32
    float* rsA  = mcA + 32;                        // 32

    const int tid = threadIdx.x, wid = tid >> 5, lane = tid & 31;
    const bool isL1 = blockIdx.x >= 32;
    const int c = isL1 ? (int)blockIdx.x - 32 : (int)blockIdx.x;

    float creg[4] = {0.f, 0.f, 0.f, 0.f};

    for (int t = 0; t <= Tn; t++) {
        if (!isL1 && t < Tn) {
            const int u = t;
            const unsigned char* Ah = g_W0f + (size_t)c * 262144;
            const unsigned char* Bg = g_h0B[u & 1];
            const int mt = wid & 7, nh = wid >> 3;
            const int cpo = tid * 64;              // 512 thr x 64B = 32KB chunk
#pragma unroll
            for (int k0 = 0; k0 < 2; k0++) {
                const unsigned char* src = Bg + k0 * 32768 + cpo;
                uint32_t dst = smem_u32(sm + k0 * 32768 + cpo);
#pragma unroll
                for (int i = 0; i < 4; i++) cpa16(dst + i * 16, src + i * 16);
                CP_COMMIT();
            }
            uint4 ahc = *(const uint4*)(Ah + ((size_t)mt << 9) + lane * 16);
            float acc[4][4] = {};
            for (int kt = 0; kt < 64; kt++) {
                int kc = kt >> 4;
                if ((kt & 15) == 0) {
                    if (kc < 3) { CP_WAIT(1); } else { CP_WAIT(0); }
                    __syncthreads();
                }
                uint4 ahn;
                if (kt < 63)
                    ahn = *(const uint4*)(Ah + ((size_t)((kt + 1) * 8 + mt) << 9) + lane * 16);
                const unsigned char* bb = sm + (kc & 1) * 32768 + ((kt & 15) << 11) + (nh << 10);
                uint2 bh[4];
#pragma unroll
                for (int j = 0; j < 4; j++)
                    bh[j] = *(const uint2*)(bb + (j << 8) + lane * 8);
#pragma unroll
                for (int j = 0; j < 4; j++) MMAH(acc[j], ahc, bh[j]);
                if ((kt & 15) == 15) {
                    __syncthreads();
                    if (kc + 2 < 4) {
                        const unsigned char* src = Bg + (kc + 2) * 32768 + cpo;
                        uint32_t dst = smem_u32(sm + (kc & 1) * 32768 + cpo);
#pragma unroll
                        for (int i = 0; i < 4; i++) cpa16(dst + i * 16, src + i * 16);
                        CP_COMMIT();
                    }
                }
                ahc = ahn;
            }
            __syncthreads();
            // ---------------- epilogue L0 ----------------
#pragma unroll
            for (int j = 0; j < 4; j++) {
                int r0 = mt * 16 + (lane >> 2);
                int cl = (nh * 4 + j) * 8 + (lane & 3) * 2;
                Cs[r0][cl] = acc[j][0]; Cs[r0][cl + 1] = acc[j][1];
                Cs[r0 + 8][cl] = acc[j][2]; Cs[r0 + 8][cl + 1] = acc[j][3];
            }
            __syncthreads();
            {   // BN row pass: 4 threads per row
                int r = tid >> 2, q = tid & 3;
                float s = 0.f, s2 = 0.f;
#pragma unroll
                for (int i = 0; i < 16; i++) {
                    float v = Cs[r][q * 16 + i]; s += v; s2 += v * v;
                }
                s  += __shfl_xor_sync(0xffffffffu, s, 1);
                s  += __shfl_xor_sync(0xffffffffu, s, 2);
                s2 += __shfl_xor_sync(0xffffffffu, s2, 1);
                s2 += __shfl_xor_sync(0xffffffffu, s2, 2);
                float m = s * (1.f / 64.f);
                float var = fmaxf(s2 * (1.f / 64.f) - m * m, 0.f);
                float gam = gh0[(r >> 5) * Hn + c * 32 + (r & 31)];
                float sc = gam * rsqrtf(var + 1e-5f);
#pragma unroll
                for (int i = 0; i < 16; i++)
                    Cs[r][q * 16 + i] = sc * (Cs[r][q * 16 + i] - m);
            }
            __syncthreads();
            int hcl = tid & 31, bg = tid >> 5;     // 16 b-groups of 4
            int hc = c * 32 + hcl;
            float ov[4], ps = 0.f, p2 = 0.f;
            float bI = b0[hc], bJ = b0[Hn + hc], bF = b0[2 * Hn + hc], bO = b0[3 * Hn + hc];
#pragma unroll
            for (int i = 0; i < 4; i++) {
                int b = bg * 4 + i;
                const float* gx = g_GX0 + (size_t)(u * 64 + b) * FH;
                float preI = Cs[hcl][b]      + gx[hc]          + bI;
                float preJ = Cs[32 + hcl][b] + gx[Hn + hc]     + bJ;
                float preF = Cs[64 + hcl][b] + gx[2 * Hn + hc] + bF;
                float preO = Cs[96 + hcl][b] + gx[3 * Hn + hc] + bO;
                float cn = sigm(preF + 1.f) * creg[i] + sigm(preI) * tanhf(preJ);
                creg[i] = cn; ov[i] = preO; ps += cn; p2 += cn * cn;
            }
            psA[bg * 32 + hcl] = ps; ps2A[bg * 32 + hcl] = p2;
            __syncthreads();
            if (tid < 32) {
                float s = 0.f, s2 = 0.f;
#pragma unroll
                for (int g = 0; g < 16; g++) { s += psA[g * 32 + tid]; s2 += ps2A[g * 32 + tid]; }
                float m = s * (1.f / 64.f);
                float var = fmaxf(s2 * (1.f / 64.f) - m * m, 0.f);
                mcA[tid] = m; rsA[tid] = rsqrtf(var + 1e-5f);
            }
            __syncthreads();
            float gcv = gc0[hc], bcv = bc0[hc], mm = mcA[hcl], rr = rsA[hcl];
            unsigned char* hb = g_h0B[(u + 1) & 1];
#pragma unroll
            for (int i = 0; i < 4; i++) {
                float cn = gcv * (creg[i] - mm) * rr + bcv;
                float h = sigm(ov[i]) * tanhf(cn);
                write_hfrag(hb, bg * 4 + i, hc, h);
            }
        } else if (isL1 && t >= 1) {
            const int u = t - 1;
            const int g = wid >> 3, mt = (wid >> 1) & 3, nh = wid & 1;
            const unsigned char* Ag = (g == 0 ? g_W1xf : g_W1hf) + (size_t)c * 131072;
            const unsigned char* BB[2] = { g_h0B[(u + 1) & 1], g_h1B[u & 1] };
            const int gsel = g * 16384;
            const int sg = tid >> 8, cpo = (tid & 255) * 64;  // 256 thr x 64B = 16KB per gemm
#pragma unroll
            for (int k0 = 0; k0 < 2; k0++) {
                const unsigned char* src = BB[sg] + k0 * 16384 + cpo;
                uint32_t dst = smem_u32(sm + k0 * 32768 + sg * 16384 + cpo);
#pragma unroll
                for (int i = 0; i < 4; i++) cpa16(dst + i * 16, src + i * 16);
                CP_COMMIT();
            }
            uint4 ahc = *(const uint4*)(Ag + ((size_t)mt << 9) + lane * 16);
            float acc[4][4] = {};
            for (int kt = 0; kt < 64; kt++) {
                int kc = kt >> 3;
                if ((kt & 7) == 0) {
                    if (kc < 7) { CP_WAIT(1); } else { CP_WAIT(0); }
                    __syncthreads();
                }
                uint4 ahn;
                if (kt < 63)
                    ahn = *(const uint4*)(Ag + ((size_t)((kt + 1) * 4 + mt) << 9) + lane * 16);
                const unsigned char* bb = sm + (kc & 1) * 32768 + gsel + ((kt & 7) << 11) + (nh << 10);
                uint2 bh[4];
#pragma unroll
                for (int j = 0; j < 4; j++)
                    bh[j] = *(const uint2*)(bb + (j << 8) + lane * 8);
#pragma unroll
                for (int j = 0; j < 4; j++) MMAH(acc[j], ahc, bh[j]);
                if ((kt & 7) == 7) {
                    __syncthreads();
                    if (kc + 2 < 8) {
                        const unsigned char* src = BB[sg] + (kc + 2) * 16384 + cpo;
                        uint32_t dst = smem_u32(sm + (kc & 1) * 32768 + sg * 16384 + cpo);
#pragma unroll
                        for (int i = 0; i < 4; i++) cpa16(dst + i * 16, src + i * 16);
                        CP_COMMIT();
                    }
                }
                ahc = ahn;
            }
            __syncthreads();
            // ---------------- epilogue L1 ----------------
#pragma unroll
            for (int j = 0; j < 4; j++) {
                int r0 = g * 64 + mt * 16 + (lane >> 2);
                int cl = (nh * 4 + j) * 8 + (lane & 3) * 2;
                Cs[r0][cl] = acc[j][0]; Cs[r0][cl + 1] = acc[j][1];
                Cs[r0 + 8][cl] = acc[j][2]; Cs[r0 + 8][cl + 1] = acc[j][3];
            }
            __syncthreads();
            {   // BN row pass: 4 threads per row
                int r = tid >> 2, q = tid & 3, rr = r & 63;
                float s = 0.f, s2 = 0.f;
#pragma unroll
                for (int i = 0; i < 16; i++) {
                    float v = Cs[r][q * 16 + i]; s += v; s2 += v * v;
                }
                s  += __shfl_xor_sync(0xffffffffu, s, 1);
                s  += __shfl_xor_sync(0xffffffffu, s, 2);
                s2 += __shfl_xor_sync(0xffffffffu, s2, 1);
                s2 += __shfl_xor_sync(0xffffffffu, s2, 2);
                float m = s * (1.f / 64.f);
                float var = fmaxf(s2 * (1.f / 64.f) - m * m, 0.f);
                int gi = (rr >> 4) * Hn + c * 16 + (rr & 15);
                float gam = (r < 64) ? gx1[gi] : gh1[gi];
                float sc = gam * rsqrtf(var + 1e-5f);
#pragma unroll
                for (int i = 0; i < 16; i++)
                    Cs[r][q * 16 + i] = sc * (Cs[r][q * 16 + i] - m);
            }
            __syncthreads();
            int hcl = tid & 15, bg = tid >> 4;     // 32 b-groups of 2
            int hc = c * 16 + hcl;
            float ov[2], ps = 0.f, p2 = 0.f;
            float bI = b1[hc], bJ = b1[Hn + hc], bF = b1[2 * Hn + hc], bO = b1[3 * Hn + hc];
#pragma unroll
            for (int i = 0; i < 2; i++) {
                int b = bg * 2 + i;
                float preI = Cs[hcl][b]      + Cs[64 + hcl][b]  + bI;
                float preJ = Cs[16 + hcl][b] + Cs[80 + hcl][b]  + bJ;
                float preF = Cs[32 + hcl][b] + Cs[96 + hcl][b]  + bF;
                float preO = Cs[48 + hcl][b] + Cs[112 + hcl][b] + bO;
                float cn = sigm(preF + 1.f) * creg[i] + sigm(preI) * tanhf(preJ);
                creg[i] = cn; ov[i] = preO; ps += cn; p2 += cn * cn;
            }
            psA[bg * 16 + hcl] = ps; ps2A[bg * 16 + hcl] = p2;
            __syncthreads();
            if (tid < 16) {
                float s = 0.f, s2 = 0.f;
#pragma unroll
                for (int gg = 0; gg < 32; gg++) { s += psA[gg * 16 + tid]; s2 += ps2A[gg * 16 + tid]; }
                float m = s * (1.f / 64.f);
                float var = fmaxf(s2 * (1.f / 64.f) - m * m, 0.f);
                mcA[tid] = m; rsA[tid] = rsqrtf(var + 1e-5f);
            }
            __syncthreads();
            float gcv = gc1[hc], bcv = bc1[hc], mm = mcA[hcl], rr = rsA[hcl];
            unsigned char* hb = g_h1B[(u + 1) & 1];
#pragma unroll
            for (int i = 0; i < 2; i++) {
                int b = bg * 2 + i;
                float cn = gcv * (creg[i] - mm) * rr + bcv;
                float h = sigm(ov[i]) * tanhf(cn);
                write_hfrag(hb, b, hc, h);
                g_H1[((size_t)b * Tn + u) * Hn + hc] = h;
            }
        }
        grid_bar();
    }
}

// ------------------------------ launch ------------------------------------
extern "C" void kernel_launch(void* const* d_in, const int* in_sizes, int n_in,
                              void* d_out, int out_size) {
    const int*   inp = (const int*)  d_in[0];
    const float* emb = (const float*)d_in[1];
    const float* Wx0 = (const float*)d_in[2];
    const float* Wh0 = (const float*)d_in[3];
    const float* b0  = (const float*)d_in[4];
    const float* gx0 = (const float*)d_in[5];
    const float* gh0 = (const float*)d_in[6];
    const float* gc0 = (const float*)d_in[7];
    const float* bc0 = (const float*)d_in[8];
    const float* Wx1 = (const float*)d_in[9];
    const float* Wh1 = (const float*)d_in[10];
    const float* b1  = (const float*)d_in[11];
    const float* gx1 = (const float*)d_in[12];
    const float* gh1 = (const float*)d_in[13];
    const float* gc1 = (const float*)d_in[14];
    const float* bc1 = (const float*)d_in[15];
    const float* Wp  = (const float*)d_in[16];
    const float* bp  = (const float*)d_in[17];
    const float* sw  = (const float*)d_in[18];
    const float* sb  = (const float*)d_in[19];
    float* out = (float*)d_out;

    float *pGX0, *pH1, *pY;
    unsigned char *pXf, *pYf, *pWx0B, *pswB;
    cudaGetSymbolAddress((void**)&pGX0, g_GX0);
    cudaGetSymbolAddress((void**)&pH1,  g_H1);
    cudaGetSymbolAddress((void**)&pY,   g_Y);
    cudaGetSymbolAddress((void**)&pXf,  g_Xf);
    cudaGetSymbolAddress((void**)&pYf,  g_Yf);
    cudaGetSymbolAddress((void**)&pWx0B, g_Wx0B);
    cudaGetSymbolAddress((void**)&pswB,  g_swB);

    cudaFuncSetAttribute(k_scan, cudaFuncAttributeMaxDynamicSharedMemorySize, 69888);
    cudaFuncSetAttribute(k_gemm_mma, cudaFuncAttributeMaxDynamicSharedMemorySize, 65536);

    // launch order arranged so k_scan is the 6th launch (ncu -s 5 -c 1)
    k_embed<<<Tn * Bn, 256>>>(inp, emb);                        // 1 (init fused)
    k_prepw<<<dim3(16384, 3), 256>>>(Wh0, Wx1, Wh1);            // 2
    k_prepB<<<(NUn * (FH + Vn)) / 256, 256>>>(Wx0, sw);         // 3
    k_gemm_mma<<<dim3(FH / 64, 64), 256, 65536>>>(pXf, pWx0B, nullptr, pGX0, FH);  // 4
    k_bnx<<<(Tn * FH) / 256, 256>>>(gx0);                       // 5
    k_scan<<<NBLK, 512, 69888>>>(b0, gh0, gc0, bc0, b1, gx1, gh1, gc1, bc1);       // 6
    k_gemm<<<dim3(NUn / 64, (Tn * Bn) / 128), 256>>>(pH1, Wp, bp, pY,
                                                     Tn * Bn, NUn, Hn);
    k_fragA<<<Tn * Bn, 256>>>(pY);
    k_gemm_mma<<<dim3(Vn / 64, 64), 256, 65536>>>(pYf, pswB, sb, out, Vn);
}